// round 1
// baseline (speedup 1.0000x reference)
#include <cuda_runtime.h>
#include <math.h>

#define BATCH 2
#define SEQ   16384
#define EMB   512
#define HEADS 8
#define HD    64
#define MF    64
#define NROWS (BATCH*SEQ)      // 32768
#define BH    (BATCH*HEADS)    // 16
#define NCHUNK 16
#define SCHUNK (SEQ/NCHUNK)    // 1024

// ---------------- scratch (device globals: allocation-free) ----------------
__device__ float g_Q[NROWS*EMB];
__device__ float g_K[NROWS*EMB];
__device__ float g_V[NROWS*EMB];
__device__ float g_attn[NROWS*EMB];
__device__ float g_Qphi[(long)BH*SEQ*MF];
__device__ float g_Kphi[(long)BH*SEQ*MF];
__device__ float g_KVp[BH*NCHUNK*MF*HD];
__device__ float g_Konesp[BH*NCHUNK*MF];
__device__ float g_KV[BH*MF*HD];
__device__ float g_Kones[BH*MF];

// ---------------- classic 128x128x16 SGEMM, 8x8 per thread ----------------
// C[M,N] = alpha * A[M,K] @ B[K,N], all row-major, M%128==N%128==K%16==0
__global__ __launch_bounds__(256) void sgemm128(
    const float* __restrict__ A, const float* __restrict__ B,
    float* __restrict__ C, int N, int K, float alpha)
{
    __shared__ float As[16][128];
    __shared__ float Bs[16][128];
    const int tid = threadIdx.x;
    const long row0 = (long)blockIdx.y * 128;
    const int  col0 = blockIdx.x * 128;
    const int tr = (tid >> 4) * 4;   // row offset within tile (split 0..63 / 64..127)
    const int tc = (tid & 15) * 4;   // col offset within tile (split)

    float acc[8][8];
#pragma unroll
    for (int i = 0; i < 8; i++)
#pragma unroll
        for (int j = 0; j < 8; j++) acc[i][j] = 0.f;

    const float* Ab = A + row0 * K;
    const float* Bb = B + col0;

    for (int k0 = 0; k0 < K; k0 += 16) {
#pragma unroll
        for (int i = 0; i < 2; i++) {
            int f  = tid + i * 256;          // 0..511 float4 slots
            int r  = f >> 2, c4 = f & 3;     // A tile: 128 rows x 4 float4
            float4 va = *reinterpret_cast<const float4*>(Ab + (long)r * K + k0 + c4 * 4);
            As[c4*4+0][r] = va.x; As[c4*4+1][r] = va.y;
            As[c4*4+2][r] = va.z; As[c4*4+3][r] = va.w;
            int rb = f >> 5, cb = f & 31;    // B tile: 16 rows x 32 float4
            *reinterpret_cast<float4*>(&Bs[rb][cb*4]) =
                *reinterpret_cast<const float4*>(Bb + (long)(k0 + rb) * N + cb * 4);
        }
        __syncthreads();
#pragma unroll
        for (int kk = 0; kk < 16; kk++) {
            float ar[8], br[8];
            *reinterpret_cast<float4*>(ar)     = *reinterpret_cast<const float4*>(&As[kk][tr]);
            *reinterpret_cast<float4*>(ar + 4) = *reinterpret_cast<const float4*>(&As[kk][64 + tr]);
            *reinterpret_cast<float4*>(br)     = *reinterpret_cast<const float4*>(&Bs[kk][tc]);
            *reinterpret_cast<float4*>(br + 4) = *reinterpret_cast<const float4*>(&Bs[kk][64 + tc]);
#pragma unroll
            for (int i = 0; i < 8; i++)
#pragma unroll
                for (int j = 0; j < 8; j++)
                    acc[i][j] = fmaf(ar[i], br[j], acc[i][j]);
        }
        __syncthreads();
    }
#pragma unroll
    for (int i = 0; i < 8; i++) {
        long gr = row0 + ((i < 4) ? (tr + i) : (64 + tr + i - 4));
        float4 v0 = make_float4(alpha*acc[i][0], alpha*acc[i][1], alpha*acc[i][2], alpha*acc[i][3]);
        float4 v1 = make_float4(alpha*acc[i][4], alpha*acc[i][5], alpha*acc[i][6], alpha*acc[i][7]);
        *reinterpret_cast<float4*>(C + gr * N + col0 + tc)      = v0;
        *reinterpret_cast<float4*>(C + gr * N + col0 + 64 + tc) = v1;
    }
}

// ---------------- positive random-feature map ----------------
// For each (b,h,s): phi[m] = max(exp(-0.5*l2^2), eps) * exp(min(v@omega, 50))
// proj layout: [b*S+s][E] with head h at cols h*64..; phi layout: [(b*H+h)*S+s][M]
__global__ __launch_bounds__(256) void feature_map(
    const float* __restrict__ proj, const float* __restrict__ omega,
    float* __restrict__ phi)
{
    __shared__ float oms[HD][MF];
    __shared__ float sv[4][HD];
    const int tid = threadIdx.x;
#pragma unroll
    for (int i = 0; i < 16; i++) {
        int idx = tid + i * 256;
        oms[idx >> 6][idx & 63] = omega[idx];
    }
    const int sub = tid >> 6;
    const int t   = tid & 63;
    const long rowid = (long)blockIdx.x * 4 + sub;   // over B*H*S
    const int b = (int)(rowid / ((long)HEADS * SEQ));
    const int h = (int)((rowid / SEQ) % HEADS);
    const int s = (int)(rowid % SEQ);
    const float* vptr = proj + ((long)b * SEQ + s) * EMB + h * HD;
    sv[sub][t] = vptr[t];
    __syncthreads();

    float f = 0.f, l2sq = 0.f;
#pragma unroll
    for (int d = 0; d < HD; d++) {
        float vd = sv[sub][d];
        f    = fmaf(vd, oms[d][t], f);
        l2sq = fmaf(vd, vd, l2sq);
    }
    f = fminf(f, 50.0f);
    float l2 = fmaxf(sqrtf(l2sq), 1e-8f);
    float nt = fmaxf(expf(-0.5f * l2 * l2), 1e-8f);
    phi[rowid * MF + t] = nt * expf(f);
}

// ---------------- KV = K_phi^T @ V and K_ones = sum_s K_phi (split-K partials)
__global__ __launch_bounds__(256) void kv_partial(
    const float* __restrict__ Kphi, const float* __restrict__ V,
    float* __restrict__ KVp, float* __restrict__ Konesp)
{
    __shared__ float Ks[32][MF];
    __shared__ float Vs[32][HD];
    const int tid = threadIdx.x;
    const int bh = blockIdx.y;
    const int part = blockIdx.x;
    const int b = bh / HEADS, h = bh % HEADS;
    const int s0 = part * SCHUNK;
    const int tr = (tid >> 4) * 4;   // m
    const int tc = (tid & 15) * 4;   // d
    float acc[4][4];
#pragma unroll
    for (int i = 0; i < 4; i++)
#pragma unroll
        for (int j = 0; j < 4; j++) acc[i][j] = 0.f;
    float kon = 0.f;

    for (int ss = 0; ss < SCHUNK; ss += 32) {
#pragma unroll
        for (int i = 0; i < 2; i++) {
            int f = tid + i * 256;           // 512 float4 slots: 32 rows x 16 f4
            int r = f >> 4, c = (f & 15) * 4;
            long s = (long)s0 + ss + r;
            *reinterpret_cast<float4*>(&Ks[r][c]) =
                *reinterpret_cast<const float4*>(Kphi + ((long)bh * SEQ + s) * MF + c);
            *reinterpret_cast<float4*>(&Vs[r][c]) =
                *reinterpret_cast<const float4*>(V + ((long)b * SEQ + s) * EMB + h * HD + c);
        }
        __syncthreads();
#pragma unroll
        for (int k = 0; k < 32; k++) {
            float a[4], bb[4];
            *reinterpret_cast<float4*>(a)  = *reinterpret_cast<const float4*>(&Ks[k][tr]);
            *reinterpret_cast<float4*>(bb) = *reinterpret_cast<const float4*>(&Vs[k][tc]);
#pragma unroll
            for (int i = 0; i < 4; i++)
#pragma unroll
                for (int j = 0; j < 4; j++)
                    acc[i][j] = fmaf(a[i], bb[j], acc[i][j]);
        }
        if (tid < MF) {
#pragma unroll
            for (int k = 0; k < 32; k++) kon += Ks[k][tid];
        }
        __syncthreads();
    }
    float* dst = KVp + ((long)bh * NCHUNK + part) * (MF * HD);
#pragma unroll
    for (int i = 0; i < 4; i++) {
        float4 v = make_float4(acc[i][0], acc[i][1], acc[i][2], acc[i][3]);
        *reinterpret_cast<float4*>(dst + (tr + i) * HD + tc) = v;
    }
    if (tid < MF) Konesp[((long)bh * NCHUNK + part) * MF + tid] = kon;
}

// ---------------- deterministic reduce of partials ----------------
__global__ __launch_bounds__(256) void kv_reduce(
    const float* __restrict__ KVp, const float* __restrict__ Konesp,
    float* __restrict__ KV, float* __restrict__ Kones)
{
    const int bh = blockIdx.x, tid = threadIdx.x;
    for (int idx = tid; idx < MF * HD; idx += 256) {
        float s = 0.f;
#pragma unroll
        for (int p = 0; p < NCHUNK; p++)
            s += KVp[((long)bh * NCHUNK + p) * (MF * HD) + idx];
        KV[bh * MF * HD + idx] = s;
    }
    if (tid < MF) {
        float s = 0.f;
#pragma unroll
        for (int p = 0; p < NCHUNK; p++)
            s += Konesp[((long)bh * NCHUNK + p) * MF + tid];
        Kones[bh * MF + tid] = s;
    }
}

// ---------------- attn = (Q_phi @ KV) / (Q_phi @ K_ones) ----------------
__global__ __launch_bounds__(256) void qkv_attn(
    const float* __restrict__ Qphi, const float* __restrict__ KV,
    const float* __restrict__ Kones, float* __restrict__ attn)
{
    __shared__ float KVs[MF][HD];
    __shared__ float ko[MF];
    __shared__ float q[4][MF];
    const int tid = threadIdx.x;
    const int bh = blockIdx.y;
    const int b = bh / HEADS, h = bh % HEADS;
    const int s0 = blockIdx.x * 256;
#pragma unroll
    for (int i = 0; i < 4; i++) {
        int f = tid + i * 256;               // 1024 float4 slots: 64 rows x 16 f4
        int m = f >> 4, c = (f & 15) * 4;
        *reinterpret_cast<float4*>(&KVs[m][c]) =
            *reinterpret_cast<const float4*>(KV + (long)bh * MF * HD + m * HD + c);
    }
    if (tid < MF) ko[tid] = Kones[bh * MF + tid];
    __syncthreads();

    const int sub = tid >> 6, t = tid & 63;
    for (int ss = 0; ss < 256; ss += 4) {
        int s = s0 + ss + sub;
        q[sub][t] = Qphi[((long)bh * SEQ + s) * MF + t];
        __syncthreads();
        float num = 0.f, den = 0.f;
#pragma unroll
        for (int m = 0; m < MF; m++) {
            float qm = q[sub][m];
            den = fmaf(qm, ko[m], den);
            num = fmaf(qm, KVs[m][t], num);
        }
        attn[((long)b * SEQ + s) * EMB + h * HD + t] = num / den;
        __syncthreads();
    }
}

// ---------------- launch ----------------
extern "C" void kernel_launch(void* const* d_in, const int* in_sizes, int n_in,
                              void* d_out, int out_size)
{
    const float* x   = (const float*)d_in[0];
    const float* Wq  = (const float*)d_in[1];
    const float* Wk  = (const float*)d_in[2];
    const float* Wv  = (const float*)d_in[3];
    const float* Wo  = (const float*)d_in[4];
    const float* omq = (const float*)d_in[5];
    const float* omk = (const float*)d_in[6];
    float* out = (float*)d_out;

    float *pQ, *pK, *pV, *pAttn, *pQphi, *pKphi, *pKVp, *pKonesp, *pKV, *pKones;
    cudaGetSymbolAddress((void**)&pQ,     g_Q);
    cudaGetSymbolAddress((void**)&pK,     g_K);
    cudaGetSymbolAddress((void**)&pV,     g_V);
    cudaGetSymbolAddress((void**)&pAttn,  g_attn);
    cudaGetSymbolAddress((void**)&pQphi,  g_Qphi);
    cudaGetSymbolAddress((void**)&pKphi,  g_Kphi);
    cudaGetSymbolAddress((void**)&pKVp,   g_KVp);
    cudaGetSymbolAddress((void**)&pKonesp,g_Konesp);
    cudaGetSymbolAddress((void**)&pKV,    g_KV);
    cudaGetSymbolAddress((void**)&pKones, g_Kones);

    const float scale = 0.125f;  // 1/sqrt(D), D=64
    dim3 gproj(EMB / 128, NROWS / 128);  // (4, 256)

    sgemm128<<<gproj, 256>>>(x, Wq, pQ, EMB, EMB, scale);
    sgemm128<<<gproj, 256>>>(x, Wk, pK, EMB, EMB, scale);
    sgemm128<<<gproj, 256>>>(x, Wv, pV, EMB, EMB, 1.0f);

    feature_map<<<(BH * SEQ) / 4, 256>>>(pQ, omq, pQphi);
    feature_map<<<(BH * SEQ) / 4, 256>>>(pK, omk, pKphi);

    kv_partial<<<dim3(NCHUNK, BH), 256>>>(pKphi, pV, pKVp, pKonesp);
    kv_reduce<<<BH, 256>>>(pKVp, pKonesp, pKV, pKones);

    qkv_attn<<<dim3(SEQ / 256, BH), 256>>>(pQphi, pKV, pKones, pAttn);

    sgemm128<<<gproj, 256>>>(pAttn, Wo, out, EMB, EMB, 1.0f);
}

// round 4
// speedup vs baseline: 1.5050x; 1.5050x over previous
#include <cuda_runtime.h>
#include <cuda_fp16.h>
#include <math.h>
#include <stdint.h>

#define BATCH 2
#define SEQ   16384
#define EMB   512
#define HEADS 8
#define HD    64
#define MF    64
#define NROWS 32768          // BATCH*SEQ
#define BH    16
#define KSP   1536           // 3*EMB (hi|hi|lo split along K)
#define NC1   2560           // [Q|K|V|Fq|Fk] columns
#define NCHUNK 16
#define SCHUNK 1024

// ---------------- device scratch ----------------
// g_Xsp doubles as x-split (before gemm1) and attn-split (after gemm1).
__device__ __align__(1024) __half g_Xsp[(long)NROWS * KSP];
__device__ __align__(1024) float  g_Weff[EMB * NC1];
__device__ __align__(1024) __half g_Wsp1[(long)NC1 * KSP];
__device__ __align__(1024) __half g_Wsp2[(long)EMB * KSP];
__device__ __align__(1024) float  g_Y[(long)NROWS * NC1];
__device__ __align__(1024) float  g_Qphi[(long)BH * SEQ * MF];
__device__ __align__(1024) float  g_Kphi[(long)BH * SEQ * MF];
__device__ __align__(1024) float  g_KVp[BH * NCHUNK * MF * HD];
__device__ __align__(1024) float  g_Konesp[BH * NCHUNK * MF];
__device__ __align__(1024) float  g_KV[BH * MF * HD];
__device__ __align__(1024) float  g_Kones[BH * MF];

// ---------------- helpers ----------------
__device__ __forceinline__ uint32_t smem_u32(const void* p) {
    uint32_t a;
    asm("{ .reg .u64 t; cvta.to.shared.u64 t, %1; cvt.u32.u64 %0, t; }" : "=r"(a) : "l"(p));
    return a;
}
#define CP16(dst, src)   asm volatile("cp.async.cg.shared.global [%0], [%1], 16;" :: "r"(dst), "l"(src))
#define CP_COMMIT()      asm volatile("cp.async.commit_group;" ::: "memory")
#define CP_WAIT1()       asm volatile("cp.async.wait_group 1;" ::: "memory")
#define CP_WAIT0()       asm volatile("cp.async.wait_group 0;" ::: "memory")

__device__ __forceinline__ void mma16816(float* c, const uint32_t* a, const uint32_t* b) {
    asm volatile(
        "mma.sync.aligned.m16n8k16.row.col.f32.f16.f16.f32 "
        "{%0,%1,%2,%3}, {%4,%5,%6,%7}, {%8,%9}, {%0,%1,%2,%3};"
        : "+f"(c[0]), "+f"(c[1]), "+f"(c[2]), "+f"(c[3])
        : "r"(a[0]), "r"(a[1]), "r"(a[2]), "r"(a[3]), "r"(b[0]), "r"(b[1]));
}

// ---------------- prep: split x into [hi|hi|lo] fp16 ----------------
__global__ __launch_bounds__(256) void split_x(const float* __restrict__ x,
                                               __half* __restrict__ o) {
    long idx = (long)blockIdx.x * 256 + threadIdx.x;   // over NROWS*EMB
    long row = idx >> 9; int col = (int)(idx & 511);
    float v = x[idx];
    __half hi = __float2half_rn(v);
    __half lo = __float2half_rn(v - __half2float(hi));
    long ob = row * KSP + col;
    o[ob] = hi; o[ob + 512] = hi; o[ob + 1024] = lo;
}

// ---------------- prep: W_eff[k][n] = [s*Wq | s*Wk | Wv | s*Wq@omq | s*Wk@omk]
__global__ __launch_bounds__(256) void prep_weff(
    const float* __restrict__ Wq, const float* __restrict__ Wk,
    const float* __restrict__ Wv, const float* __restrict__ omq,
    const float* __restrict__ omk, float* __restrict__ Weff) {
    __shared__ float om[2][HD * MF];
    const int k = blockIdx.y;
    const int n = blockIdx.x * 256 + threadIdx.x;
    if (blockIdx.x >= 6) {
        for (int i = threadIdx.x; i < HD * MF; i += 256) {
            om[0][i] = omq[i]; om[1][i] = omk[i];
        }
        __syncthreads();
    }
    float r;
    if (n < 512)       r = Wq[k * 512 + n] * 0.125f;
    else if (n < 1024) r = Wk[k * 512 + n - 512] * 0.125f;
    else if (n < 1536) r = Wv[k * 512 + n - 1024];
    else {
        int nn = n - 1536;
        const float* W = (nn < 512) ? Wq : Wk;
        const float* o = om[(nn < 512) ? 0 : 1];
        nn &= 511;
        int h = nn >> 6, m = nn & 63;
        float s = 0.f;
#pragma unroll
        for (int d = 0; d < HD; d++)
            s = fmaf(W[k * 512 + h * 64 + d], o[d * 64 + m], s);
        r = s * 0.125f;
    }
    Weff[k * NC1 + n] = r;
}

// ---------------- prep: transpose + split W [512 x N] -> Wsp [N x 1536] hi|lo|hi
__global__ void tsplit(const float* __restrict__ W, int N, __half* __restrict__ Wsp) {
    __shared__ float t[32][33];
    const int k0 = blockIdx.y * 32, n0 = blockIdx.x * 32;
#pragma unroll
    for (int i = 0; i < 4; i++) {
        int r = threadIdx.y + i * 8;
        t[r][threadIdx.x] = W[(k0 + r) * N + n0 + threadIdx.x];
    }
    __syncthreads();
#pragma unroll
    for (int i = 0; i < 4; i++) {
        int n = threadIdx.y + i * 8, k = threadIdx.x;
        float v = t[k][n];
        __half hi = __float2half_rn(v);
        __half lo = __float2half_rn(v - __half2float(hi));
        long ob = (long)(n0 + n) * KSP + k0 + k;
        Wsp[ob] = hi; Wsp[ob + 512] = lo; Wsp[ob + 1024] = hi;
    }
}

// ---------------- HMMA GEMM: C[M x N] = A[M x 1536] @ B[N x 1536]^T ----------------
// block 128x256, K-chunk 64, 8 warps (warp tile 64x64), cp.async double buffer.
#define BM 128
#define BN 256
#define BK 64
#define SAW 72                        // padded halves per smem row (36 words: conflict-free)
#define STAGEB ((BM + BN) * SAW * 2)  // 55296 bytes per stage
#define KCH (KSP / BK)                // 24

__global__ void __launch_bounds__(256, 1) gemm_mma(
    const __half* __restrict__ A, const __half* __restrict__ B,
    float* __restrict__ C, int ldC) {
    extern __shared__ __align__(16) char smraw[];
    const uint32_t sb = smem_u32(smraw);
    const int tid = threadIdx.x, wid = tid >> 5, lane = tid & 31;
    const int wr = wid >> 2, wc = wid & 3;     // warp grid 2x4
    const long row0 = (long)blockIdx.y * BM;
    const int  col0 = blockIdx.x * BN;

    const __half* Ag = A + row0 * KSP;
    const __half* Bg = B + (long)col0 * KSP;

    // loader lambda: chunk ch -> stage s
    auto load_tiles = [&](int ch, int s) {
        uint32_t abase = sb + s * STAGEB;
        uint32_t bbase = abase + BM * SAW * 2;
        const __half* Asrc = Ag + ch * BK;
        const __half* Bsrc = Bg + ch * BK;
#pragma unroll
        for (int i = 0; i < 4; i++) {               // A: 128 rows x 4 chunks16B
            int f = tid + i * 256; int r = f >> 3, c = f & 7;
            CP16(abase + r * (SAW * 2) + c * 16, Asrc + (long)r * KSP + c * 8);
        }
#pragma unroll
        for (int i = 0; i < 8; i++) {               // B: 256 rows x 4 chunks16B
            int f = tid + i * 256; int r = f >> 3, c = f & 7;
            CP16(bbase + r * (SAW * 2) + c * 16, Bsrc + (long)r * KSP + c * 8);
        }
    };

    float acc[4][8][4];
#pragma unroll
    for (int i = 0; i < 4; i++)
#pragma unroll
        for (int j = 0; j < 8; j++)
#pragma unroll
            for (int t = 0; t < 4; t++) acc[i][j][t] = 0.f;

    load_tiles(0, 0);
    CP_COMMIT();

    const int qr = lane >> 2;        // 0..7
    const int qc = (lane & 3) * 2;   // 0,2,4,6

    for (int ch = 0; ch < KCH; ch++) {
        const int st = ch & 1;
        if (ch + 1 < KCH) { load_tiles(ch + 1, st ^ 1); CP_COMMIT(); CP_WAIT1(); }
        else              { CP_WAIT0(); }
        __syncthreads();

        const __half* As = (const __half*)(smraw + st * STAGEB);
        const __half* Bs = As + BM * SAW;
#pragma unroll
        for (int kk = 0; kk < BK; kk += 16) {
            uint32_t af[4][4], bf[8][2];
#pragma unroll
            for (int mi = 0; mi < 4; mi++) {
                int r = wr * 64 + mi * 16 + qr;
                const __half* p = As + r * SAW + kk + qc;
                af[mi][0] = *(const uint32_t*)p;
                af[mi][1] = *(const uint32_t*)(p + 8 * SAW);
                af[mi][2] = *(const uint32_t*)(p + 8);
                af[mi][3] = *(const uint32_t*)(p + 8 * SAW + 8);
            }
#pragma unroll
            for (int ni = 0; ni < 8; ni++) {
                int n = wc * 64 + ni * 8 + qr;
                const __half* p = Bs + n * SAW + kk + qc;
                bf[ni][0] = *(const uint32_t*)p;
                bf[ni][1] = *(const uint32_t*)(p + 8);
            }
#pragma unroll
            for (int mi = 0; mi < 4; mi++)
#pragma unroll
                for (int ni = 0; ni < 8; ni++)
                    mma16816(acc[mi][ni], af[mi], bf[ni]);
        }
        __syncthreads();
    }

    // epilogue
#pragma unroll
    for (int mi = 0; mi < 4; mi++) {
        long r0 = row0 + wr * 64 + mi * 16 + qr;
#pragma unroll
        for (int ni = 0; ni < 8; ni++) {
            int cb = col0 + wc * 64 + ni * 8 + qc;
            *(float2*)(C + r0 * ldC + cb)       = make_float2(acc[mi][ni][0], acc[mi][ni][1]);
            *(float2*)(C + (r0 + 8) * ldC + cb) = make_float2(acc[mi][ni][2], acc[mi][ni][3]);
        }
    }
}

// ---------------- phi: row-norm + exp, from Y sections ----------------
__global__ __launch_bounds__(256) void phi_kernel(
    const float* __restrict__ Y, float* __restrict__ Qphi, float* __restrict__ Kphi) {
    long gw = (long)blockIdx.x * 8 + (threadIdx.x >> 5);   // global warp over NROWS*16
    int lane = threadIdx.x & 31;
    long r = gw >> 4;
    int rem = (int)(gw & 15);
    int qk = rem >> 3, h = rem & 7;
    const float* y = Y + r * NC1 + qk * 512 + h * 64;
    float v0 = y[lane], v1 = y[lane + 32];
    float nsq = v0 * v0 + v1 * v1;
#pragma unroll
    for (int m = 16; m >= 1; m >>= 1) nsq += __shfl_xor_sync(0xffffffffu, nsq, m);
    float nt = fmaxf(expf(-0.5f * nsq), 1e-8f);
    const float* fy = Y + r * NC1 + 1536 + qk * 512 + h * 64;
    float f0 = fy[lane], f1 = fy[lane + 32];
    int b = (int)(r >> 14), s = (int)(r & 16383);
    float* dst = (qk == 0 ? Qphi : Kphi) + (((long)b * HEADS + h) * SEQ + s) * MF;
    dst[lane]      = nt * expf(fminf(f0, 50.0f));
    dst[lane + 32] = nt * expf(fminf(f1, 50.0f));
}

// ---------------- KV partials (V read from Y section) ----------------
__global__ __launch_bounds__(256) void kv_partial(
    const float* __restrict__ Kphi, const float* __restrict__ Y,
    float* __restrict__ KVp, float* __restrict__ Konesp) {
    __shared__ float Ks[32][MF];
    __shared__ float Vs[32][HD];
    const int tid = threadIdx.x;
    const int bh = blockIdx.y, part = blockIdx.x;
    const int b = bh / HEADS, h = bh % HEADS;
    const int s0 = part * SCHUNK;
    const int tr = (tid >> 4) * 4, tc = (tid & 15) * 4;
    float acc[4][4];
#pragma unroll
    for (int i = 0; i < 4; i++)
#pragma unroll
        for (int j = 0; j < 4; j++) acc[i][j] = 0.f;
    float kon = 0.f;

    for (int ss = 0; ss < SCHUNK; ss += 32) {
#pragma unroll
        for (int i = 0; i < 2; i++) {
            int f = tid + i * 256;
            int r = f >> 4, c = (f & 15) * 4;
            long s = (long)s0 + ss + r;
            *reinterpret_cast<float4*>(&Ks[r][c]) =
                *reinterpret_cast<const float4*>(Kphi + ((long)bh * SEQ + s) * MF + c);
            *reinterpret_cast<float4*>(&Vs[r][c]) =
                *reinterpret_cast<const float4*>(Y + ((long)b * SEQ + s) * NC1 + 1024 + h * HD + c);
        }
        __syncthreads();
#pragma unroll
        for (int k = 0; k < 32; k++) {
            float a[4], bb[4];
            *reinterpret_cast<float4*>(a)  = *reinterpret_cast<const float4*>(&Ks[k][tr]);
            *reinterpret_cast<float4*>(bb) = *reinterpret_cast<const float4*>(&Vs[k][tc]);
#pragma unroll
            for (int i = 0; i < 4; i++)
#pragma unroll
                for (int j = 0; j < 4; j++)
                    acc[i][j] = fmaf(a[i], bb[j], acc[i][j]);
        }
        if (tid < MF) {
#pragma unroll
            for (int k = 0; k < 32; k++) kon += Ks[k][tid];
        }
        __syncthreads();
    }
    float* dst = KVp + ((long)bh * NCHUNK + part) * (MF * HD);
#pragma unroll
    for (int i = 0; i < 4; i++) {
        float4 v = make_float4(acc[i][0], acc[i][1], acc[i][2], acc[i][3]);
        *reinterpret_cast<float4*>(dst + (tr + i) * HD + tc) = v;
    }
    if (tid < MF) Konesp[((long)bh * NCHUNK + part) * MF + tid] = kon;
}

__global__ __launch_bounds__(256) void kv_reduce(
    const float* __restrict__ KVp, const float* __restrict__ Konesp,
    float* __restrict__ KV, float* __restrict__ Kones) {
    const int bh = blockIdx.x, tid = threadIdx.x;
    for (int idx = tid; idx < MF * HD; idx += 256) {
        float s = 0.f;
#pragma unroll
        for (int p = 0; p < NCHUNK; p++)
            s += KVp[((long)bh * NCHUNK + p) * (MF * HD) + idx];
        KV[bh * MF * HD + idx] = s;
    }
    if (tid < MF) {
        float s = 0.f;
#pragma unroll
        for (int p = 0; p < NCHUNK; p++)
            s += Konesp[((long)bh * NCHUNK + p) * MF + tid];
        Kones[bh * MF + tid] = s;
    }
}

// ---------------- attn = (Qphi@KV)/(Qphi@Kones), written as split fp16 ----------------
__global__ __launch_bounds__(256) void qkv_attn(
    const float* __restrict__ Qphi, const float* __restrict__ KV,
    const float* __restrict__ Kones, __half* __restrict__ Asp) {
    __shared__ float KVs[MF][HD];
    __shared__ float ko[MF];
    __shared__ float q[4][MF];
    const int tid = threadIdx.x;
    const int bh = blockIdx.y;
    const int b = bh / HEADS, h = bh % HEADS;
    const int s0 = blockIdx.x * 256;
#pragma unroll
    for (int i = 0; i < 4; i++) {
        int f = tid + i * 256;
        int m = f >> 4, c = (f & 15) * 4;
        *reinterpret_cast<float4*>(&KVs[m][c]) =
            *reinterpret_cast<const float4*>(KV + (long)bh * MF * HD + m * HD + c);
    }
    if (tid < MF) ko[tid] = Kones[bh * MF + tid];
    __syncthreads();

    const int sub = tid >> 6, t = tid & 63;
    for (int ss = 0; ss < 256; ss += 4) {
        int s = s0 + ss + sub;
        q[sub][t] = Qphi[((long)bh * SEQ + s) * MF + t];
        __syncthreads();
        float num = 0.f, den = 0.f;
#pragma unroll
        for (int m = 0; m < MF; m++) {
            float qm = q[sub][m];
            den = fmaf(qm, ko[m], den);
            num = fmaf(qm, KVs[m][t], num);
        }
        float a = num / den;
        __half hi = __float2half_rn(a);
        __half lo = __float2half_rn(a - __half2float(hi));
        long ob = ((long)b * SEQ + s) * KSP + h * HD + t;
        Asp[ob] = hi; Asp[ob + 512] = hi; Asp[ob + 1024] = lo;
        __syncthreads();
    }
}

// ---------------- launch ----------------
extern "C" void kernel_launch(void* const* d_in, const int* in_sizes, int n_in,
                              void* d_out, int out_size) {
    const float* x   = (const float*)d_in[0];
    const float* Wq  = (const float*)d_in[1];
    const float* Wk  = (const float*)d_in[2];
    const float* Wv  = (const float*)d_in[3];
    const float* Wo  = (const float*)d_in[4];
    const float* omq = (const float*)d_in[5];
    const float* omk = (const float*)d_in[6];
    float* out = (float*)d_out;

    __half *pXsp, *pWsp1, *pWsp2;
    float *pWeff, *pY, *pQphi, *pKphi, *pKVp, *pKonesp, *pKV, *pKones;
    cudaGetSymbolAddress((void**)&pXsp,   g_Xsp);
    cudaGetSymbolAddress((void**)&pWeff,  g_Weff);
    cudaGetSymbolAddress((void**)&pWsp1,  g_Wsp1);
    cudaGetSymbolAddress((void**)&pWsp2,  g_Wsp2);
    cudaGetSymbolAddress((void**)&pY,     g_Y);
    cudaGetSymbolAddress((void**)&pQphi,  g_Qphi);
    cudaGetSymbolAddress((void**)&pKphi,  g_Kphi);
    cudaGetSymbolAddress((void**)&pKVp,   g_KVp);
    cudaGetSymbolAddress((void**)&pKonesp,g_Konesp);
    cudaGetSymbolAddress((void**)&pKV,    g_KV);
    cudaGetSymbolAddress((void**)&pKones, g_Kones);

    cudaFuncSetAttribute(gemm_mma, cudaFuncAttributeMaxDynamicSharedMemorySize, 2 * STAGEB);

    split_x<<<(NROWS * EMB) / 256, 256>>>(x, pXsp);
    prep_weff<<<dim3(NC1 / 256, EMB), 256>>>(Wq, Wk, Wv, omq, omk, pWeff);
    tsplit<<<dim3(NC1 / 32, EMB / 32), dim3(32, 8)>>>(pWeff, NC1, pWsp1);
    tsplit<<<dim3(EMB / 32, EMB / 32), dim3(32, 8)>>>(Wo, EMB, pWsp2);

    gemm_mma<<<dim3(NC1 / BN, NROWS / BM), 256, 2 * STAGEB>>>(pXsp, pWsp1, pY, NC1);

    phi_kernel<<<(NROWS * 16) / 8, 256>>>(pY, pQphi, pKphi);

    kv_partial<<<dim3(NCHUNK, BH), 256>>>(pKphi, pY, pKVp, pKonesp);
    kv_reduce<<<BH, 256>>>(pKVp, pKonesp, pKV, pKones);
    // g_Xsp is dead after gemm1 -> reuse it for the attn split
    qkv_attn<<<dim3(SEQ / 256, BH), 256>>>(pQphi, pKV, pKones, pXsp);

    gemm_mma<<<dim3(EMB / BN, NROWS / BM), 256, 2 * STAGEB>>>(pXsp, pWsp2, out, EMB);
}

// round 5
// speedup vs baseline: 1.6928x; 1.1248x over previous
#include <cuda_runtime.h>
#include <cuda_fp16.h>
#include <math.h>
#include <stdint.h>

#define BATCH 2
#define SEQ   16384
#define EMB   512
#define HEADS 8
#define HD    64
#define MF    64
#define NROWS 32768          // BATCH*SEQ
#define BH    16
#define NC1   2560           // [Q|K|V|Fq|Fk] columns
#define NCHUNK 16
#define SCHUNK 1024

// ---------------- device scratch ----------------
// g_Xhi/g_Xlo double as x-split (gemm1 A) and attn-split (gemm2 A).
__device__ __align__(1024) __half g_Xhi[(long)NROWS * EMB];
__device__ __align__(1024) __half g_Xlo[(long)NROWS * EMB];
__device__ __align__(1024) float  g_Weff[EMB * NC1];
__device__ __align__(1024) __half g_Wh1[(long)NC1 * EMB];
__device__ __align__(1024) __half g_Wl1[(long)NC1 * EMB];
__device__ __align__(1024) __half g_Wh2[EMB * EMB];
__device__ __align__(1024) __half g_Wl2[EMB * EMB];
__device__ __align__(1024) float  g_Y[(long)NROWS * NC1];
__device__ __align__(1024) float  g_Qphi[(long)BH * SEQ * MF];
__device__ __align__(1024) float  g_Kphi[(long)BH * SEQ * MF];
__device__ __align__(1024) float  g_KVp[BH * NCHUNK * MF * HD];
__device__ __align__(1024) float  g_Konesp[BH * NCHUNK * MF];
__device__ __align__(1024) float  g_KV[BH * MF * HD];
__device__ __align__(1024) float  g_Kones[BH * MF];

// ---------------- helpers ----------------
__device__ __forceinline__ uint32_t smem_u32(const void* p) {
    uint32_t a;
    asm("{ .reg .u64 t; cvta.to.shared.u64 t, %1; cvt.u32.u64 %0, t; }" : "=r"(a) : "l"(p));
    return a;
}
#define CP16(dst, src)   asm volatile("cp.async.cg.shared.global [%0], [%1], 16;" :: "r"(dst), "l"(src))
#define CP_COMMIT()      asm volatile("cp.async.commit_group;" ::: "memory")
#define CP_WAIT1()       asm volatile("cp.async.wait_group 1;" ::: "memory")
#define CP_WAIT0()       asm volatile("cp.async.wait_group 0;" ::: "memory")
#define LDSM4(r0,r1,r2,r3,addr) \
    asm volatile("ldmatrix.sync.aligned.m8n8.x4.shared.b16 {%0,%1,%2,%3}, [%4];" \
        : "=r"(r0), "=r"(r1), "=r"(r2), "=r"(r3) : "r"(addr))

__device__ __forceinline__ void mma16816(float* c, const uint32_t* a, const uint32_t* b) {
    asm volatile(
        "mma.sync.aligned.m16n8k16.row.col.f32.f16.f16.f32 "
        "{%0,%1,%2,%3}, {%4,%5,%6,%7}, {%8,%9}, {%0,%1,%2,%3};"
        : "+f"(c[0]), "+f"(c[1]), "+f"(c[2]), "+f"(c[3])
        : "r"(a[0]), "r"(a[1]), "r"(a[2]), "r"(a[3]), "r"(b[0]), "r"(b[1]));
}

// ---------------- prep: split x into hi/lo fp16 arrays ----------------
__global__ __launch_bounds__(256) void split_x(const float* __restrict__ x,
                                               __half* __restrict__ ohi,
                                               __half* __restrict__ olo) {
    long idx = (long)blockIdx.x * 256 + threadIdx.x;   // over NROWS*EMB
    float v = x[idx];
    __half hi = __float2half_rn(v);
    __half lo = __float2half_rn(v - __half2float(hi));
    ohi[idx] = hi; olo[idx] = lo;
}

// ---------------- prep: W_eff[k][n] = [s*Wq | s*Wk | Wv | s*Wq@omq | s*Wk@omk]
__global__ __launch_bounds__(256) void prep_weff(
    const float* __restrict__ Wq, const float* __restrict__ Wk,
    const float* __restrict__ Wv, const float* __restrict__ omq,
    const float* __restrict__ omk, float* __restrict__ Weff) {
    __shared__ float om[2][HD * MF];
    const int k = blockIdx.y;
    const int n = blockIdx.x * 256 + threadIdx.x;
    if (blockIdx.x >= 6) {
        for (int i = threadIdx.x; i < HD * MF; i += 256) {
            om[0][i] = omq[i]; om[1][i] = omk[i];
        }
        __syncthreads();
    }
    float r;
    if (n < 512)       r = Wq[k * 512 + n] * 0.125f;
    else if (n < 1024) r = Wk[k * 512 + n - 512] * 0.125f;
    else if (n < 1536) r = Wv[k * 512 + n - 1024];
    else {
        int nn = n - 1536;
        const float* W = (nn < 512) ? Wq : Wk;
        const float* o = om[(nn < 512) ? 0 : 1];
        nn &= 511;
        int h = nn >> 6, m = nn & 63;
        float s = 0.f;
#pragma unroll
        for (int d = 0; d < HD; d++)
            s = fmaf(W[k * 512 + h * 64 + d], o[d * 64 + m], s);
        r = s * 0.125f;
    }
    Weff[k * NC1 + n] = r;
}

// ---------------- prep: transpose + split W [512 x N] -> hi/lo [N x 512] ----------------
__global__ void tsplit(const float* __restrict__ W, int N,
                       __half* __restrict__ Whi, __half* __restrict__ Wlo) {
    __shared__ float t[32][33];
    const int k0 = blockIdx.y * 32, n0 = blockIdx.x * 32;
#pragma unroll
    for (int i = 0; i < 4; i++) {
        int r = threadIdx.y + i * 8;
        t[r][threadIdx.x] = W[(k0 + r) * N + n0 + threadIdx.x];
    }
    __syncthreads();
#pragma unroll
    for (int i = 0; i < 4; i++) {
        int n = threadIdx.y + i * 8, k = threadIdx.x;
        float v = t[k][n];
        __half hi = __float2half_rn(v);
        __half lo = __float2half_rn(v - __half2float(hi));
        long ob = (long)(n0 + n) * EMB + k0 + k;
        Whi[ob] = hi; Wlo[ob] = lo;
    }
}

// ---------------- HMMA GEMM with shared hi/lo tiles ----------------
// C[M x N] = Ahi@Bhi^T + Ahi@Blo^T + Alo@Bhi^T  over K=512
// block 128x256, K-chunk 64, 8 warps (warp tile 64x64), cp.async double buffer.
#define BM 128
#define BN 256
#define BK 64
#define ROWB 144                       // padded row bytes (72 halves)
#define A_TILE (BM * ROWB)             // 18432
#define B_TILE (BN * ROWB)             // 36864
#define STAGE  (2 * A_TILE + 2 * B_TILE)  // 110592
#define SMEMSZ (2 * STAGE)             // 221184
#define KCH (EMB / BK)                 // 8

__global__ void __launch_bounds__(256, 1) gemm_mma3(
    const __half* __restrict__ Ahi, const __half* __restrict__ Alo,
    const __half* __restrict__ Bhi, const __half* __restrict__ Blo,
    float* __restrict__ C, int ldC) {
    extern __shared__ __align__(16) char smraw[];
    const uint32_t sb = smem_u32(smraw);
    const int tid = threadIdx.x, wid = tid >> 5, lane = tid & 31;
    const int wr = wid >> 2, wc = wid & 3;     // warp grid 2x4
    const long row0 = (long)blockIdx.y * BM;
    const int  col0 = blockIdx.x * BN;

    const __half* Agh = Ahi + row0 * EMB;
    const __half* Agl = Alo + row0 * EMB;
    const __half* Bgh = Bhi + (long)col0 * EMB;
    const __half* Bgl = Blo + (long)col0 * EMB;

    auto load_tiles = [&](int ch, int s) {
        uint32_t base = sb + s * STAGE;
        const __half* asrc[2] = { Agh + ch * BK, Agl + ch * BK };
        const __half* bsrc[2] = { Bgh + ch * BK, Bgl + ch * BK };
#pragma unroll
        for (int t = 0; t < 2; t++) {
#pragma unroll
            for (int i = 0; i < 4; i++) {          // A: 128 rows x 8 c16
                int f = tid + i * 256; int r = f >> 3, c = f & 7;
                CP16(base + t * A_TILE + r * ROWB + c * 16,
                     asrc[t] + (long)r * EMB + c * 8);
            }
        }
#pragma unroll
        for (int t = 0; t < 2; t++) {
#pragma unroll
            for (int i = 0; i < 8; i++) {          // B: 256 rows x 8 c16
                int f = tid + i * 256; int r = f >> 3, c = f & 7;
                CP16(base + 2 * A_TILE + t * B_TILE + r * ROWB + c * 16,
                     bsrc[t] + (long)r * EMB + c * 8);
            }
        }
    };

    float acc[4][8][4];
#pragma unroll
    for (int i = 0; i < 4; i++)
#pragma unroll
        for (int j = 0; j < 8; j++)
#pragma unroll
            for (int t = 0; t < 4; t++) acc[i][j][t] = 0.f;

    load_tiles(0, 0);
    CP_COMMIT();

    // ldmatrix lane-address components
    const uint32_t aRow = (uint32_t)(wr * 64 + (lane & 15)) * ROWB;
    const uint32_t aCol = (uint32_t)((lane >> 4) * 8) * 2;
    const uint32_t bRow = (uint32_t)(wc * 64 + (lane & 7) + ((lane >> 4) & 1) * 8) * ROWB;
    const uint32_t bCol = (uint32_t)(((lane >> 3) & 1) * 8) * 2;

    for (int ch = 0; ch < KCH; ch++) {
        const int st = ch & 1;
        if (ch + 1 < KCH) { load_tiles(ch + 1, st ^ 1); CP_COMMIT(); CP_WAIT1(); }
        else              { CP_WAIT0(); }
        __syncthreads();

        const uint32_t stB = sb + st * STAGE;
        const uint32_t AhB = stB, AlB = stB + A_TILE;
        const uint32_t BhB = stB + 2 * A_TILE, BlB = BhB + B_TILE;
#pragma unroll
        for (int kk = 0; kk < BK; kk += 16) {
            uint32_t bh[8][2], bl[8][2], af[4][4];
#pragma unroll
            for (int np = 0; np < 4; np++) {
                uint32_t off = bRow + (uint32_t)(np * 16) * ROWB + kk * 2 + bCol;
                LDSM4(bh[2*np][0], bh[2*np][1], bh[2*np+1][0], bh[2*np+1][1], BhB + off);
                LDSM4(bl[2*np][0], bl[2*np][1], bl[2*np+1][0], bl[2*np+1][1], BlB + off);
            }
#pragma unroll
            for (int mi = 0; mi < 4; mi++) {
                uint32_t off = aRow + (uint32_t)(mi * 16) * ROWB + kk * 2 + aCol;
                LDSM4(af[mi][0], af[mi][1], af[mi][2], af[mi][3], AhB + off);
            }
#pragma unroll
            for (int mi = 0; mi < 4; mi++)
#pragma unroll
                for (int ni = 0; ni < 8; ni++) {
                    mma16816(acc[mi][ni], af[mi], bh[ni]);
                    mma16816(acc[mi][ni], af[mi], bl[ni]);
                }
#pragma unroll
            for (int mi = 0; mi < 4; mi++) {
                uint32_t off = aRow + (uint32_t)(mi * 16) * ROWB + kk * 2 + aCol;
                LDSM4(af[mi][0], af[mi][1], af[mi][2], af[mi][3], AlB + off);
            }
#pragma unroll
            for (int mi = 0; mi < 4; mi++)
#pragma unroll
                for (int ni = 0; ni < 8; ni++)
                    mma16816(acc[mi][ni], af[mi], bh[ni]);
        }
        __syncthreads();
    }

    const int qr = lane >> 2;
    const int qc = (lane & 3) * 2;
#pragma unroll
    for (int mi = 0; mi < 4; mi++) {
        long r0 = row0 + wr * 64 + mi * 16 + qr;
#pragma unroll
        for (int ni = 0; ni < 8; ni++) {
            int cb = col0 + wc * 64 + ni * 8 + qc;
            *(float2*)(C + r0 * ldC + cb)       = make_float2(acc[mi][ni][0], acc[mi][ni][1]);
            *(float2*)(C + (r0 + 8) * ldC + cb) = make_float2(acc[mi][ni][2], acc[mi][ni][3]);
        }
    }
}

// ---------------- phi: row-norm + exp, from Y sections ----------------
__global__ __launch_bounds__(256) void phi_kernel(
    const float* __restrict__ Y, float* __restrict__ Qphi, float* __restrict__ Kphi) {
    long gw = (long)blockIdx.x * 8 + (threadIdx.x >> 5);   // over NROWS*16
    int lane = threadIdx.x & 31;
    long r = gw >> 4;
    int rem = (int)(gw & 15);
    int qk = rem >> 3, h = rem & 7;
    const float* y = Y + r * NC1 + qk * 512 + h * 64;
    float v0 = y[lane], v1 = y[lane + 32];
    float nsq = v0 * v0 + v1 * v1;
#pragma unroll
    for (int m = 16; m >= 1; m >>= 1) nsq += __shfl_xor_sync(0xffffffffu, nsq, m);
    float nt = fmaxf(expf(-0.5f * nsq), 1e-8f);
    const float* fy = Y + r * NC1 + 1536 + qk * 512 + h * 64;
    float f0 = fy[lane], f1 = fy[lane + 32];
    int b = (int)(r >> 14), s = (int)(r & 16383);
    float* dst = (qk == 0 ? Qphi : Kphi) + (((long)b * HEADS + h) * SEQ + s) * MF;
    dst[lane]      = nt * expf(fminf(f0, 50.0f));
    dst[lane + 32] = nt * expf(fminf(f1, 50.0f));
}

// ---------------- KV partials (V read from Y section) ----------------
__global__ __launch_bounds__(256) void kv_partial(
    const float* __restrict__ Kphi, const float* __restrict__ Y,
    float* __restrict__ KVp, float* __restrict__ Konesp) {
    __shared__ float Ks[32][MF];
    __shared__ float Vs[32][HD];
    const int tid = threadIdx.x;
    const int bh = blockIdx.y, part = blockIdx.x;
    const int b = bh / HEADS, h = bh % HEADS;
    const int s0 = part * SCHUNK;
    const int tr = (tid >> 4) * 4, tc = (tid & 15) * 4;
    float acc[4][4];
#pragma unroll
    for (int i = 0; i < 4; i++)
#pragma unroll
        for (int j = 0; j < 4; j++) acc[i][j] = 0.f;
    float kon = 0.f;

    for (int ss = 0; ss < SCHUNK; ss += 32) {
#pragma unroll
        for (int i = 0; i < 2; i++) {
            int f = tid + i * 256;
            int r = f >> 4, c = (f & 15) * 4;
            long s = (long)s0 + ss + r;
            *reinterpret_cast<float4*>(&Ks[r][c]) =
                *reinterpret_cast<const float4*>(Kphi + ((long)bh * SEQ + s) * MF + c);
            *reinterpret_cast<float4*>(&Vs[r][c]) =
                *reinterpret_cast<const float4*>(Y + ((long)b * SEQ + s) * NC1 + 1024 + h * HD + c);
        }
        __syncthreads();
#pragma unroll
        for (int k = 0; k < 32; k++) {
            float a[4], bb[4];
            *reinterpret_cast<float4*>(a)  = *reinterpret_cast<const float4*>(&Ks[k][tr]);
            *reinterpret_cast<float4*>(bb) = *reinterpret_cast<const float4*>(&Vs[k][tc]);
#pragma unroll
            for (int i = 0; i < 4; i++)
#pragma unroll
                for (int j = 0; j < 4; j++)
                    acc[i][j] = fmaf(a[i], bb[j], acc[i][j]);
        }
        if (tid < MF) {
#pragma unroll
            for (int k = 0; k < 32; k++) kon += Ks[k][tid];
        }
        __syncthreads();
    }
    float* dst = KVp + ((long)bh * NCHUNK + part) * (MF * HD);
#pragma unroll
    for (int i = 0; i < 4; i++) {
        float4 v = make_float4(acc[i][0], acc[i][1], acc[i][2], acc[i][3]);
        *reinterpret_cast<float4*>(dst + (tr + i) * HD + tc) = v;
    }
    if (tid < MF) Konesp[((long)bh * NCHUNK + part) * MF + tid] = kon;
}

__global__ __launch_bounds__(256) void kv_reduce(
    const float* __restrict__ KVp, const float* __restrict__ Konesp,
    float* __restrict__ KV, float* __restrict__ Kones) {
    const int bh = blockIdx.x, tid = threadIdx.x;
    for (int idx = tid; idx < MF * HD; idx += 256) {
        float s = 0.f;
#pragma unroll
        for (int p = 0; p < NCHUNK; p++)
            s += KVp[((long)bh * NCHUNK + p) * (MF * HD) + idx];
        KV[bh * MF * HD + idx] = s;
    }
    if (tid < MF) {
        float s = 0.f;
#pragma unroll
        for (int p = 0; p < NCHUNK; p++)
            s += Konesp[((long)bh * NCHUNK + p) * MF + tid];
        Kones[bh * MF + tid] = s;
    }
}

// ---------------- attn = (Qphi@KV)/(Qphi@Kones), written as hi/lo fp16 ----------------
__global__ __launch_bounds__(256) void qkv_attn(
    const float* __restrict__ Qphi, const float* __restrict__ KV,
    const float* __restrict__ Kones, __half* __restrict__ Ahi,
    __half* __restrict__ Alo) {
    __shared__ float KVs[MF][HD];
    __shared__ float ko[MF];
    __shared__ float q[4][MF];
    const int tid = threadIdx.x;
    const int bh = blockIdx.y;
    const int b = bh / HEADS, h = bh % HEADS;
    const int s0 = blockIdx.x * 256;
#pragma unroll
    for (int i = 0; i < 4; i++) {
        int f = tid + i * 256;
        int m = f >> 4, c = (f & 15) * 4;
        *reinterpret_cast<float4*>(&KVs[m][c]) =
            *reinterpret_cast<const float4*>(KV + (long)bh * MF * HD + m * HD + c);
    }
    if (tid < MF) ko[tid] = Kones[bh * MF + tid];
    __syncthreads();

    const int sub = tid >> 6, t = tid & 63;
    for (int ss = 0; ss < 256; ss += 4) {
        int s = s0 + ss + sub;
        q[sub][t] = Qphi[((long)bh * SEQ + s) * MF + t];
        __syncthreads();
        float num = 0.f, den = 0.f;
#pragma unroll
        for (int m = 0; m < MF; m++) {
            float qm = q[sub][m];
            den = fmaf(qm, ko[m], den);
            num = fmaf(qm, KVs[m][t], num);
        }
        float a = num / den;
        __half hi = __float2half_rn(a);
        __half lo = __float2half_rn(a - __half2float(hi));
        long ob = ((long)b * SEQ + s) * EMB + h * HD + t;
        Ahi[ob] = hi; Alo[ob] = lo;
        __syncthreads();
    }
}

// ---------------- launch ----------------
extern "C" void kernel_launch(void* const* d_in, const int* in_sizes, int n_in,
                              void* d_out, int out_size) {
    const float* x   = (const float*)d_in[0];
    const float* Wq  = (const float*)d_in[1];
    const float* Wk  = (const float*)d_in[2];
    const float* Wv  = (const float*)d_in[3];
    const float* Wo  = (const float*)d_in[4];
    const float* omq = (const float*)d_in[5];
    const float* omk = (const float*)d_in[6];
    float* out = (float*)d_out;

    __half *pXhi, *pXlo, *pWh1, *pWl1, *pWh2, *pWl2;
    float *pWeff, *pY, *pQphi, *pKphi, *pKVp, *pKonesp, *pKV, *pKones;
    cudaGetSymbolAddress((void**)&pXhi,   g_Xhi);
    cudaGetSymbolAddress((void**)&pXlo,   g_Xlo);
    cudaGetSymbolAddress((void**)&pWeff,  g_Weff);
    cudaGetSymbolAddress((void**)&pWh1,   g_Wh1);
    cudaGetSymbolAddress((void**)&pWl1,   g_Wl1);
    cudaGetSymbolAddress((void**)&pWh2,   g_Wh2);
    cudaGetSymbolAddress((void**)&pWl2,   g_Wl2);
    cudaGetSymbolAddress((void**)&pY,     g_Y);
    cudaGetSymbolAddress((void**)&pQphi,  g_Qphi);
    cudaGetSymbolAddress((void**)&pKphi,  g_Kphi);
    cudaGetSymbolAddress((void**)&pKVp,   g_KVp);
    cudaGetSymbolAddress((void**)&pKonesp,g_Konesp);
    cudaGetSymbolAddress((void**)&pKV,    g_KV);
    cudaGetSymbolAddress((void**)&pKones, g_Kones);

    cudaFuncSetAttribute(gemm_mma3, cudaFuncAttributeMaxDynamicSharedMemorySize, SMEMSZ);

    split_x<<<(NROWS * EMB) / 256, 256>>>(x, pXhi, pXlo);
    prep_weff<<<dim3(NC1 / 256, EMB), 256>>>(Wq, Wk, Wv, omq, omk, pWeff);
    tsplit<<<dim3(NC1 / 32, EMB / 32), dim3(32, 8)>>>(pWeff, NC1, pWh1, pWl1);
    tsplit<<<dim3(EMB / 32, EMB / 32), dim3(32, 8)>>>(Wo, EMB, pWh2, pWl2);

    gemm_mma3<<<dim3(NC1 / BN, NROWS / BM), 256, SMEMSZ>>>(pXhi, pXlo, pWh1, pWl1, pY, NC1);

    phi_kernel<<<(NROWS * 16) / 8, 256>>>(pY, pQphi, pKphi);

    kv_partial<<<dim3(NCHUNK, BH), 256>>>(pKphi, pY, pKVp, pKonesp);
    kv_reduce<<<BH, 256>>>(pKVp, pKonesp, pKV, pKones);
    // g_Xhi/g_Xlo are dead after gemm1 -> reuse for attn split
    qkv_attn<<<dim3(SEQ / 256, BH), 256>>>(pQphi, pKV, pKones, pXhi, pXlo);

    gemm_mma3<<<dim3(EMB / BN, NROWS / BM), 256, SMEMSZ>>>(pXhi, pXlo, pWh2, pWl2, out, EMB);
}

// round 9
// speedup vs baseline: 2.0165x; 1.1912x over previous
#include <cuda_runtime.h>
#include <cuda_fp16.h>
#include <math.h>
#include <stdint.h>

#define BATCH 2
#define SEQ   16384
#define EMB   512
#define HEADS 8
#define HD    64
#define MF    64
#define NROWS 32768          // BATCH*SEQ
#define BH    16
#define NC1   2560           // [Q|K|V|Fq|Fk] columns
#define NCHUNK 16
#define SCHUNK 1024

// ---------------- device scratch ----------------
// g_Xh doubles as x-fp16 (gemm1 A) and attn-fp16 (gemm2 A).
__device__ __align__(1024) __half g_Xh[(long)NROWS * EMB];
__device__ __align__(1024) float  g_Weff[EMB * NC1];
__device__ __align__(1024) __half g_Wh1[(long)NC1 * EMB];
__device__ __align__(1024) __half g_Wl1[(long)NC1 * EMB];
__device__ __align__(1024) __half g_Wh2[EMB * EMB];
__device__ __align__(1024) __half g_Wl2[EMB * EMB];
__device__ __align__(1024) float  g_Y[(long)NROWS * NC1];
__device__ __align__(1024) float  g_Qphi[(long)BH * SEQ * MF];
__device__ __align__(1024) float  g_Kphi[(long)BH * SEQ * MF];
__device__ __align__(1024) float  g_KVp[BH * NCHUNK * MF * HD];
__device__ __align__(1024) float  g_Konesp[BH * NCHUNK * MF];
__device__ __align__(1024) float  g_KV[BH * MF * HD];
__device__ __align__(1024) float  g_Kones[BH * MF];

// ---------------- helpers ----------------
__device__ __forceinline__ uint32_t smem_u32(const void* p) {
    uint32_t a;
    asm("{ .reg .u64 t; cvta.to.shared.u64 t, %1; cvt.u32.u64 %0, t; }" : "=r"(a) : "l"(p));
    return a;
}
#define CP16(dst, src)   asm volatile("cp.async.cg.shared.global [%0], [%1], 16;" :: "r"(dst), "l"(src))
#define CP_COMMIT()      asm volatile("cp.async.commit_group;" ::: "memory")
#define CP_WAIT1()       asm volatile("cp.async.wait_group 1;" ::: "memory")
#define CP_WAIT0()       asm volatile("cp.async.wait_group 0;" ::: "memory")
#define LDSM4(r0,r1,r2,r3,addr) \
    asm volatile("ldmatrix.sync.aligned.m8n8.x4.shared.b16 {%0,%1,%2,%3}, [%4];" \
        : "=r"(r0), "=r"(r1), "=r"(r2), "=r"(r3) : "r"(addr))

__device__ __forceinline__ void mma16816(float* c, const uint32_t* a, const uint32_t* b) {
    asm volatile(
        "mma.sync.aligned.m16n8k16.row.col.f32.f16.f16.f32 "
        "{%0,%1,%2,%3}, {%4,%5,%6,%7}, {%8,%9}, {%0,%1,%2,%3};"
        : "+f"(c[0]), "+f"(c[1]), "+f"(c[2]), "+f"(c[3])
        : "r"(a[0]), "r"(a[1]), "r"(a[2]), "r"(a[3]), "r"(b[0]), "r"(b[1]));
}

// ---------------- prep: x -> fp16 ----------------
__global__ __launch_bounds__(256) void cvt_x(const float* __restrict__ x,
                                             __half* __restrict__ oh) {
    long idx = (long)blockIdx.x * 256 + threadIdx.x;
    oh[idx] = __float2half_rn(x[idx]);
}

// ---------------- prep: W_eff[k][n] = [s*Wq | s*Wk | Wv | s*Wq@omq | s*Wk@omk]
__global__ __launch_bounds__(256) void prep_weff(
    const float* __restrict__ Wq, const float* __restrict__ Wk,
    const float* __restrict__ Wv, const float* __restrict__ omq,
    const float* __restrict__ omk, float* __restrict__ Weff) {
    __shared__ float om[2][HD * MF];
    const int k = blockIdx.y;
    const int n = blockIdx.x * 256 + threadIdx.x;
    if (blockIdx.x >= 6) {
        for (int i = threadIdx.x; i < HD * MF; i += 256) {
            om[0][i] = omq[i]; om[1][i] = omk[i];
        }
        __syncthreads();
    }
    float r;
    if (n < 512)       r = Wq[k * 512 + n] * 0.125f;
    else if (n < 1024) r = Wk[k * 512 + n - 512] * 0.125f;
    else if (n < 1536) r = Wv[k * 512 + n - 1024];
    else {
        int nn = n - 1536;
        const float* W = (nn < 512) ? Wq : Wk;
        const float* o = om[(nn < 512) ? 0 : 1];
        nn &= 511;
        int h = nn >> 6, m = nn & 63;
        float s = 0.f;
#pragma unroll
        for (int d = 0; d < HD; d++)
            s = fmaf(W[k * 512 + h * 64 + d], o[d * 64 + m], s);
        r = s * 0.125f;
    }
    Weff[k * NC1 + n] = r;
}

// ---------------- prep: transpose + split W [512 x N] -> hi/lo [N x 512] ----------------
__global__ void tsplit(const float* __restrict__ W, int N,
                       __half* __restrict__ Whi, __half* __restrict__ Wlo) {
    __shared__ float t[32][33];
    const int k0 = blockIdx.y * 32, n0 = blockIdx.x * 32;
#pragma unroll
    for (int i = 0; i < 4; i++) {
        int r = threadIdx.y + i * 8;
        t[r][threadIdx.x] = W[(k0 + r) * N + n0 + threadIdx.x];
    }
    __syncthreads();
#pragma unroll
    for (int i = 0; i < 4; i++) {
        int n = threadIdx.y + i * 8, k = threadIdx.x;
        float v = t[k][n];
        __half hi = __float2half_rn(v);
        __half lo = __float2half_rn(v - __half2float(hi));
        long ob = (long)(n0 + n) * EMB + k0 + k;
        Whi[ob] = hi; Wlo[ob] = lo;
    }
}

// ---------------- HMMA GEMM, 2-term: C = Ah@Bhi^T + Ah@Blo^T, K=512 ----------------
// R5-proven skeleton: block 128x256, BK=64, 8 warps (warp tile 64x64),
// cp.async double buffer, 1 CTA/SM. Only change vs R5: Alo tile removed.
#define BM 128
#define BN 256
#define BK 64
#define ROWB 144                       // padded row bytes (72 halves)
#define A_TILE (BM * ROWB)             // 18432
#define B_TILE (BN * ROWB)             // 36864
#define STAGE  (A_TILE + 2 * B_TILE)   // 92160
#define SMEMSZ (2 * STAGE)             // 184320
#define KCH (EMB / BK)                 // 8

__global__ void __launch_bounds__(256, 1) gemm_mma2(
    const __half* __restrict__ Ah,
    const __half* __restrict__ Bhi, const __half* __restrict__ Blo,
    float* __restrict__ C, int ldC) {
    extern __shared__ __align__(16) char smraw[];
    const uint32_t sb = smem_u32(smraw);
    const int tid = threadIdx.x, wid = tid >> 5, lane = tid & 31;
    const int wr = wid >> 2, wc = wid & 3;     // warp grid 2x4, warp tile 64x64
    const long row0 = (long)blockIdx.y * BM;
    const int  col0 = blockIdx.x * BN;

    const __half* Ag  = Ah  + row0 * EMB;
    const __half* Bgh = Bhi + (long)col0 * EMB;
    const __half* Bgl = Blo + (long)col0 * EMB;

    auto load_tiles = [&](int ch, int s) {
        uint32_t base = sb + s * STAGE;
#pragma unroll
        for (int i = 0; i < 4; i++) {          // A: 128 rows x 8 c16
            int f = tid + i * 256; int r = f >> 3, c = f & 7;
            CP16(base + r * ROWB + c * 16, Ag + ch * BK + (long)r * EMB + c * 8);
        }
#pragma unroll
        for (int i = 0; i < 8; i++) {          // Bh: 256 rows x 8 c16
            int f = tid + i * 256; int r = f >> 3, c = f & 7;
            CP16(base + A_TILE + r * ROWB + c * 16, Bgh + ch * BK + (long)r * EMB + c * 8);
        }
#pragma unroll
        for (int i = 0; i < 8; i++) {          // Bl: 256 rows x 8 c16
            int f = tid + i * 256; int r = f >> 3, c = f & 7;
            CP16(base + A_TILE + B_TILE + r * ROWB + c * 16, Bgl + ch * BK + (long)r * EMB + c * 8);
        }
    };

    float acc[4][8][4];
#pragma unroll
    for (int i = 0; i < 4; i++)
#pragma unroll
        for (int j = 0; j < 8; j++)
#pragma unroll
            for (int t = 0; t < 4; t++) acc[i][j][t] = 0.f;

    load_tiles(0, 0);
    CP_COMMIT();

    // ldmatrix lane-address components (identical to R5)
    const uint32_t aRow = (uint32_t)(wr * 64 + (lane & 15)) * ROWB;
    const uint32_t aCol = (uint32_t)((lane >> 4) * 8) * 2;
    const uint32_t bRow = (uint32_t)(wc * 64 + (lane & 7) + ((lane >> 4) & 1) * 8) * ROWB;
    const uint32_t bCol = (uint32_t)(((lane >> 3) & 1) * 8) * 2;

    for (int ch = 0; ch < KCH; ch++) {
        const int st = ch & 1;
        if (ch + 1 < KCH) { load_tiles(ch + 1, st ^ 1); CP_COMMIT(); CP_WAIT1(); }
        else              { CP_WAIT0(); }
        __syncthreads();

        const uint32_t stB = sb + st * STAGE;
        const uint32_t AB = stB, BhB = stB + A_TILE, BlB = BhB + B_TILE;
#pragma unroll
        for (int kk = 0; kk < BK; kk += 16) {
            uint32_t af[4][4], bh[8][2], bl[8][2];
#pragma unroll
            for (int np = 0; np < 4; np++) {
                uint32_t off = bRow + (uint32_t)(np * 16) * ROWB + kk * 2 + bCol;
                LDSM4(bh[2*np][0], bh[2*np][1], bh[2*np+1][0], bh[2*np+1][1], BhB + off);
                LDSM4(bl[2*np][0], bl[2*np][1], bl[2*np+1][0], bl[2*np+1][1], BlB + off);
            }
#pragma unroll
            for (int mi = 0; mi < 4; mi++) {
                uint32_t off = aRow + (uint32_t)(mi * 16) * ROWB + kk * 2 + aCol;
                LDSM4(af[mi][0], af[mi][1], af[mi][2], af[mi][3], AB + off);
            }
#pragma unroll
            for (int mi = 0; mi < 4; mi++)
#pragma unroll
                for (int ni = 0; ni < 8; ni++) {
                    mma16816(acc[mi][ni], af[mi], bh[ni]);
                    mma16816(acc[mi][ni], af[mi], bl[ni]);
                }
        }
        __syncthreads();
    }

    const int qr = lane >> 2;
    const int qc = (lane & 3) * 2;
#pragma unroll
    for (int mi = 0; mi < 4; mi++) {
        long r0 = row0 + wr * 64 + mi * 16 + qr;
#pragma unroll
        for (int ni = 0; ni < 8; ni++) {
            int cb = col0 + wc * 64 + ni * 8 + qc;
            *(float2*)(C + r0 * ldC + cb)       = make_float2(acc[mi][ni][0], acc[mi][ni][1]);
            *(float2*)(C + (r0 + 8) * ldC + cb) = make_float2(acc[mi][ni][2], acc[mi][ni][3]);
        }
    }
}

// ---------------- phi: row-norm + exp, from Y sections ----------------
__global__ __launch_bounds__(256) void phi_kernel(
    const float* __restrict__ Y, float* __restrict__ Qphi, float* __restrict__ Kphi) {
    long gw = (long)blockIdx.x * 8 + (threadIdx.x >> 5);
    int lane = threadIdx.x & 31;
    long r = gw >> 4;
    int rem = (int)(gw & 15);
    int qk = rem >> 3, h = rem & 7;
    const float* y = Y + r * NC1 + qk * 512 + h * 64;
    float v0 = y[lane], v1 = y[lane + 32];
    float nsq = v0 * v0 + v1 * v1;
#pragma unroll
    for (int m = 16; m >= 1; m >>= 1) nsq += __shfl_xor_sync(0xffffffffu, nsq, m);
    float nt = fmaxf(expf(-0.5f * nsq), 1e-8f);
    const float* fy = Y + r * NC1 + 1536 + qk * 512 + h * 64;
    float f0 = fy[lane], f1 = fy[lane + 32];
    int b = (int)(r >> 14), s = (int)(r & 16383);
    float* dst = (qk == 0 ? Qphi : Kphi) + (((long)b * HEADS + h) * SEQ + s) * MF;
    dst[lane]      = nt * expf(fminf(f0, 50.0f));
    dst[lane + 32] = nt * expf(fminf(f1, 50.0f));
}

// ---------------- KV partials (V read from Y section) ----------------
__global__ __launch_bounds__(256) void kv_partial(
    const float* __restrict__ Kphi, const float* __restrict__ Y,
    float* __restrict__ KVp, float* __restrict__ Konesp) {
    __shared__ float Ks[32][MF];
    __shared__ float Vs[32][HD];
    const int tid = threadIdx.x;
    const int bh = blockIdx.y, part = blockIdx.x;
    const int b = bh / HEADS, h = bh % HEADS;
    const int s0 = part * SCHUNK;
    const int tr = (tid >> 4) * 4, tc = (tid & 15) * 4;
    float acc[4][4];
#pragma unroll
    for (int i = 0; i < 4; i++)
#pragma unroll
        for (int j = 0; j < 4; j++) acc[i][j] = 0.f;
    float kon = 0.f;

    for (int ss = 0; ss < SCHUNK; ss += 32) {
#pragma unroll
        for (int i = 0; i < 2; i++) {
            int f = tid + i * 256;
            int r = f >> 4, c = (f & 15) * 4;
            long s = (long)s0 + ss + r;
            *reinterpret_cast<float4*>(&Ks[r][c]) =
                *reinterpret_cast<const float4*>(Kphi + ((long)bh * SEQ + s) * MF + c);
            *reinterpret_cast<float4*>(&Vs[r][c]) =
                *reinterpret_cast<const float4*>(Y + ((long)b * SEQ + s) * NC1 + 1024 + h * HD + c);
        }
        __syncthreads();
#pragma unroll
        for (int k = 0; k < 32; k++) {
            float a[4], bb[4];
            *reinterpret_cast<float4*>(a)  = *reinterpret_cast<const float4*>(&Ks[k][tr]);
            *reinterpret_cast<float4*>(bb) = *reinterpret_cast<const float4*>(&Vs[k][tc]);
#pragma unroll
            for (int i = 0; i < 4; i++)
#pragma unroll
                for (int j = 0; j < 4; j++)
                    acc[i][j] = fmaf(a[i], bb[j], acc[i][j]);
        }
        if (tid < MF) {
#pragma unroll
            for (int k = 0; k < 32; k++) kon += Ks[k][tid];
        }
        __syncthreads();
    }
    float* dst = KVp + ((long)bh * NCHUNK + part) * (MF * HD);
#pragma unroll
    for (int i = 0; i < 4; i++) {
        float4 v = make_float4(acc[i][0], acc[i][1], acc[i][2], acc[i][3]);
        *reinterpret_cast<float4*>(dst + (tr + i) * HD + tc) = v;
    }
    if (tid < MF) Konesp[((long)bh * NCHUNK + part) * MF + tid] = kon;
}

__global__ __launch_bounds__(256) void kv_reduce(
    const float* __restrict__ KVp, const float* __restrict__ Konesp,
    float* __restrict__ KV, float* __restrict__ Kones) {
    const int bh = blockIdx.x, tid = threadIdx.x;
    for (int idx = tid; idx < MF * HD; idx += 256) {
        float s = 0.f;
#pragma unroll
        for (int p = 0; p < NCHUNK; p++)
            s += KVp[((long)bh * NCHUNK + p) * (MF * HD) + idx];
        KV[bh * MF * HD + idx] = s;
    }
    if (tid < MF) {
        float s = 0.f;
#pragma unroll
        for (int p = 0; p < NCHUNK; p++)
            s += Konesp[((long)bh * NCHUNK + p) * MF + tid];
        Kones[bh * MF + tid] = s;
    }
}

// ---------------- attn = (Qphi@KV)/(Qphi@Kones), written as fp16 ----------------
__global__ __launch_bounds__(256) void qkv_attn(
    const float* __restrict__ Qphi, const float* __restrict__ KV,
    const float* __restrict__ Kones, __half* __restrict__ Ah) {
    __shared__ float KVs[MF][HD];
    __shared__ float ko[MF];
    __shared__ float q[4][MF];
    const int tid = threadIdx.x;
    const int bh = blockIdx.y;
    const int b = bh / HEADS, h = bh % HEADS;
    const int s0 = blockIdx.x * 256;
#pragma unroll
    for (int i = 0; i < 4; i++) {
        int f = tid + i * 256;
        int m = f >> 4, c = (f & 15) * 4;
        *reinterpret_cast<float4*>(&KVs[m][c]) =
            *reinterpret_cast<const float4*>(KV + (long)bh * MF * HD + m * HD + c);
    }
    if (tid < MF) ko[tid] = Kones[bh * MF + tid];
    __syncthreads();

    const int sub = tid >> 6, t = tid & 63;
    for (int ss = 0; ss < 256; ss += 4) {
        int s = s0 + ss + sub;
        q[sub][t] = Qphi[((long)bh * SEQ + s) * MF + t];
        __syncthreads();
        float num = 0.f, den = 0.f;
#pragma unroll
        for (int m = 0; m < MF; m++) {
            float qm = q[sub][m];
            den = fmaf(qm, ko[m], den);
            num = fmaf(qm, KVs[m][t], num);
        }
        Ah[((long)b * SEQ + s) * EMB + h * HD + t] = __float2half_rn(num / den);
        __syncthreads();
    }
}

// ---------------- launch ----------------
extern "C" void kernel_launch(void* const* d_in, const int* in_sizes, int n_in,
                              void* d_out, int out_size) {
    const float* x   = (const float*)d_in[0];
    const float* Wq  = (const float*)d_in[1];
    const float* Wk  = (const float*)d_in[2];
    const float* Wv  = (const float*)d_in[3];
    const float* Wo  = (const float*)d_in[4];
    const float* omq = (const float*)d_in[5];
    const float* omk = (const float*)d_in[6];
    float* out = (float*)d_out;

    __half *pXh, *pWh1, *pWl1, *pWh2, *pWl2;
    float *pWeff, *pY, *pQphi, *pKphi, *pKVp, *pKonesp, *pKV, *pKones;
    cudaGetSymbolAddress((void**)&pXh,    g_Xh);
    cudaGetSymbolAddress((void**)&pWeff,  g_Weff);
    cudaGetSymbolAddress((void**)&pWh1,   g_Wh1);
    cudaGetSymbolAddress((void**)&pWl1,   g_Wl1);
    cudaGetSymbolAddress((void**)&pWh2,   g_Wh2);
    cudaGetSymbolAddress((void**)&pWl2,   g_Wl2);
    cudaGetSymbolAddress((void**)&pY,     g_Y);
    cudaGetSymbolAddress((void**)&pQphi,  g_Qphi);
    cudaGetSymbolAddress((void**)&pKphi,  g_Kphi);
    cudaGetSymbolAddress((void**)&pKVp,   g_KVp);
    cudaGetSymbolAddress((void**)&pKonesp,g_Konesp);
    cudaGetSymbolAddress((void**)&pKV,    g_KV);
    cudaGetSymbolAddress((void**)&pKones, g_Kones);

    cudaFuncSetAttribute(gemm_mma2, cudaFuncAttributeMaxDynamicSharedMemorySize, SMEMSZ);

    cvt_x<<<(NROWS * EMB) / 256, 256>>>(x, pXh);
    prep_weff<<<dim3(NC1 / 256, EMB), 256>>>(Wq, Wk, Wv, omq, omk, pWeff);
    tsplit<<<dim3(NC1 / 32, EMB / 32), dim3(32, 8)>>>(pWeff, NC1, pWh1, pWl1);
    tsplit<<<dim3(EMB / 32, EMB / 32), dim3(32, 8)>>>(Wo, EMB, pWh2, pWl2);

    gemm_mma2<<<dim3(NC1 / BN, NROWS / BM), 256, SMEMSZ>>>(pXh, pWh1, pWl1, pY, NC1);

    phi_kernel<<<(NROWS * 16) / 8, 256>>>(pY, pQphi, pKphi);

    kv_partial<<<dim3(NCHUNK, BH), 256>>>(pKphi, pY, pKVp, pKonesp);
    kv_reduce<<<BH, 256>>>(pKVp, pKonesp, pKV, pKones);
    // g_Xh dead after gemm1 -> reuse for attn fp16
    qkv_attn<<<dim3(SEQ / 256, BH), 256>>>(pQphi, pKV, pKones, pXh);

    gemm_mma2<<<dim3(EMB / BN, NROWS / BM), 256, SMEMSZ>>>(pXh, pWh2, pWl2, out, EMB);
}

// round 10
// speedup vs baseline: 2.5339x; 1.2566x over previous
#include <cuda_runtime.h>
#include <cuda_fp16.h>
#include <math.h>
#include <stdint.h>

#define BATCH 2
#define SEQ   16384
#define EMB   512
#define HEADS 8
#define HD    64
#define MF    64
#define NROWS 32768          // BATCH*SEQ
#define BH    16
#define NC1   1536           // [Q|K|V] columns (omega handled by phi_mma now)
#define NCHUNK 16
#define SCHUNK 1024

// ---------------- device scratch ----------------
// g_Xh doubles as x-fp16 (gemm1 A) and attn-fp16 (gemm2 A).
__device__ __align__(1024) __half g_Xh[(long)NROWS * EMB];
__device__ __align__(1024) float  g_Weff[EMB * NC1];
__device__ __align__(1024) __half g_Wh1[(long)NC1 * EMB];
__device__ __align__(1024) __half g_Wl1[(long)NC1 * EMB];
__device__ __align__(1024) __half g_Wh2[EMB * EMB];
__device__ __align__(1024) __half g_Wl2[EMB * EMB];
__device__ __align__(1024) __half g_omT[2 * HD * MF];   // fp16 omega^T [qk][m][d]
__device__ __align__(1024) float  g_Y[(long)NROWS * NC1];
__device__ __align__(1024) float  g_Qphi[(long)BH * SEQ * MF];
__device__ __align__(1024) float  g_Kphi[(long)BH * SEQ * MF];
__device__ __align__(1024) float  g_KVp[BH * NCHUNK * MF * HD];
__device__ __align__(1024) float  g_Konesp[BH * NCHUNK * MF];
__device__ __align__(1024) float  g_KV[BH * MF * HD];
__device__ __align__(1024) float  g_Kones[BH * MF];

// ---------------- helpers ----------------
__device__ __forceinline__ uint32_t smem_u32(const void* p) {
    uint32_t a;
    asm("{ .reg .u64 t; cvta.to.shared.u64 t, %1; cvt.u32.u64 %0, t; }" : "=r"(a) : "l"(p));
    return a;
}
#define CP16(dst, src)   asm volatile("cp.async.cg.shared.global [%0], [%1], 16;" :: "r"(dst), "l"(src))
#define CP_COMMIT()      asm volatile("cp.async.commit_group;" ::: "memory")
#define CP_WAIT1()       asm volatile("cp.async.wait_group 1;" ::: "memory")
#define CP_WAIT0()       asm volatile("cp.async.wait_group 0;" ::: "memory")
#define LDSM4(r0,r1,r2,r3,addr) \
    asm volatile("ldmatrix.sync.aligned.m8n8.x4.shared.b16 {%0,%1,%2,%3}, [%4];" \
        : "=r"(r0), "=r"(r1), "=r"(r2), "=r"(r3) : "r"(addr))

__device__ __forceinline__ void mma16816(float* c, const uint32_t* a, const uint32_t* b) {
    asm volatile(
        "mma.sync.aligned.m16n8k16.row.col.f32.f16.f16.f32 "
        "{%0,%1,%2,%3}, {%4,%5,%6,%7}, {%8,%9}, {%0,%1,%2,%3};"
        : "+f"(c[0]), "+f"(c[1]), "+f"(c[2]), "+f"(c[3])
        : "r"(a[0]), "r"(a[1]), "r"(a[2]), "r"(a[3]), "r"(b[0]), "r"(b[1]));
}

// ---------------- prep: x -> fp16 ----------------
__global__ __launch_bounds__(256) void cvt_x(const float* __restrict__ x,
                                             __half* __restrict__ oh) {
    long idx = (long)blockIdx.x * 256 + threadIdx.x;
    oh[idx] = __float2half_rn(x[idx]);
}

// ---------------- prep: omega [d][m] fp32 -> omega^T [m][d] fp16 ----------------
__global__ __launch_bounds__(256) void cvt_omega(const float* __restrict__ omq,
                                                 const float* __restrict__ omk,
                                                 __half* __restrict__ omT) {
    int i = blockIdx.x * 256 + threadIdx.x;     // over 2*4096
    int qk = i >> 12, e = i & 4095;
    int m = e >> 6, d = e & 63;
    const float* src = qk ? omk : omq;
    omT[qk * 4096 + m * 64 + d] = __float2half_rn(src[d * 64 + m]);
}

// ---------------- prep: W_eff[k][n] = [s*Wq | s*Wk | Wv] ----------------
__global__ __launch_bounds__(256) void prep_weff(
    const float* __restrict__ Wq, const float* __restrict__ Wk,
    const float* __restrict__ Wv, float* __restrict__ Weff) {
    const int k = blockIdx.y;
    const int n = blockIdx.x * 256 + threadIdx.x;
    float r;
    if (n < 512)       r = Wq[k * 512 + n] * 0.125f;
    else if (n < 1024) r = Wk[k * 512 + n - 512] * 0.125f;
    else               r = Wv[k * 512 + n - 1024];
    Weff[k * NC1 + n] = r;
}

// ---------------- prep: transpose + split W [512 x N] -> hi/lo [N x 512] ----------------
__global__ void tsplit(const float* __restrict__ W, int N,
                       __half* __restrict__ Whi, __half* __restrict__ Wlo) {
    __shared__ float t[32][33];
    const int k0 = blockIdx.y * 32, n0 = blockIdx.x * 32;
#pragma unroll
    for (int i = 0; i < 4; i++) {
        int r = threadIdx.y + i * 8;
        t[r][threadIdx.x] = W[(k0 + r) * N + n0 + threadIdx.x];
    }
    __syncthreads();
#pragma unroll
    for (int i = 0; i < 4; i++) {
        int n = threadIdx.y + i * 8, k = threadIdx.x;
        float v = t[k][n];
        __half hi = __float2half_rn(v);
        __half lo = __float2half_rn(v - __half2float(hi));
        long ob = (long)(n0 + n) * EMB + k0 + k;
        Whi[ob] = hi; Wlo[ob] = lo;
    }
}

// ---------------- HMMA GEMM, 2-term (R9-proven skeleton; two-pass MMA order) ----------------
#define BM 128
#define BN 256
#define BK 64
#define ROWB 144                       // padded row bytes (72 halves)
#define A_TILE (BM * ROWB)             // 18432
#define B_TILE (BN * ROWB)             // 36864
#define STAGE  (A_TILE + 2 * B_TILE)   // 92160
#define SMEMSZ (2 * STAGE)             // 184320
#define KCH (EMB / BK)                 // 8

__global__ void __launch_bounds__(256, 1) gemm_mma2(
    const __half* __restrict__ Ah,
    const __half* __restrict__ Bhi, const __half* __restrict__ Blo,
    float* __restrict__ C, int ldC) {
    extern __shared__ __align__(16) char smraw[];
    const uint32_t sb = smem_u32(smraw);
    const int tid = threadIdx.x, wid = tid >> 5, lane = tid & 31;
    const int wr = wid >> 2, wc = wid & 3;     // warp grid 2x4, warp tile 64x64
    const long row0 = (long)blockIdx.y * BM;
    const int  col0 = blockIdx.x * BN;

    const __half* Ag  = Ah  + row0 * EMB;
    const __half* Bgh = Bhi + (long)col0 * EMB;
    const __half* Bgl = Blo + (long)col0 * EMB;

    auto load_tiles = [&](int ch, int s) {
        uint32_t base = sb + s * STAGE;
#pragma unroll
        for (int i = 0; i < 4; i++) {          // A: 128 rows x 8 c16
            int f = tid + i * 256; int r = f >> 3, c = f & 7;
            CP16(base + r * ROWB + c * 16, Ag + ch * BK + (long)r * EMB + c * 8);
        }
#pragma unroll
        for (int i = 0; i < 8; i++) {          // Bh: 256 rows x 8 c16
            int f = tid + i * 256; int r = f >> 3, c = f & 7;
            CP16(base + A_TILE + r * ROWB + c * 16, Bgh + ch * BK + (long)r * EMB + c * 8);
        }
#pragma unroll
        for (int i = 0; i < 8; i++) {          // Bl: 256 rows x 8 c16
            int f = tid + i * 256; int r = f >> 3, c = f & 7;
            CP16(base + A_TILE + B_TILE + r * ROWB + c * 16, Bgl + ch * BK + (long)r * EMB + c * 8);
        }
    };

    float acc[4][8][4];
#pragma unroll
    for (int i = 0; i < 4; i++)
#pragma unroll
        for (int j = 0; j < 8; j++)
#pragma unroll
            for (int t = 0; t < 4; t++) acc[i][j][t] = 0.f;

    load_tiles(0, 0);
    CP_COMMIT();

    const uint32_t aRow = (uint32_t)(wr * 64 + (lane & 15)) * ROWB;
    const uint32_t aCol = (uint32_t)((lane >> 4) * 8) * 2;
    const uint32_t bRow = (uint32_t)(wc * 64 + (lane & 7) + ((lane >> 4) & 1) * 8) * ROWB;
    const uint32_t bCol = (uint32_t)(((lane >> 3) & 1) * 8) * 2;

    for (int ch = 0; ch < KCH; ch++) {
        const int st = ch & 1;
        if (ch + 1 < KCH) { load_tiles(ch + 1, st ^ 1); CP_COMMIT(); CP_WAIT1(); }
        else              { CP_WAIT0(); }
        __syncthreads();

        const uint32_t stB = sb + st * STAGE;
        const uint32_t AB = stB, BhB = stB + A_TILE, BlB = BhB + B_TILE;
#pragma unroll
        for (int kk = 0; kk < BK; kk += 16) {
            uint32_t af[4][4], bh[8][2], bl[8][2];
#pragma unroll
            for (int np = 0; np < 4; np++) {
                uint32_t off = bRow + (uint32_t)(np * 16) * ROWB + kk * 2 + bCol;
                LDSM4(bh[2*np][0], bh[2*np][1], bh[2*np+1][0], bh[2*np+1][1], BhB + off);
                LDSM4(bl[2*np][0], bl[2*np][1], bl[2*np+1][0], bl[2*np+1][1], BlB + off);
            }
#pragma unroll
            for (int mi = 0; mi < 4; mi++) {
                uint32_t off = aRow + (uint32_t)(mi * 16) * ROWB + kk * 2 + aCol;
                LDSM4(af[mi][0], af[mi][1], af[mi][2], af[mi][3], AB + off);
            }
            // pass 1: hi weights (dependent MMAs now 32 apart, not adjacent)
#pragma unroll
            for (int mi = 0; mi < 4; mi++)
#pragma unroll
                for (int ni = 0; ni < 8; ni++)
                    mma16816(acc[mi][ni], af[mi], bh[ni]);
            // pass 2: lo weights
#pragma unroll
            for (int mi = 0; mi < 4; mi++)
#pragma unroll
                for (int ni = 0; ni < 8; ni++)
                    mma16816(acc[mi][ni], af[mi], bl[ni]);
        }
        __syncthreads();
    }

    const int qr = lane >> 2;
    const int qc = (lane & 3) * 2;
#pragma unroll
    for (int mi = 0; mi < 4; mi++) {
        long r0 = row0 + wr * 64 + mi * 16 + qr;
#pragma unroll
        for (int ni = 0; ni < 8; ni++) {
            int cb = col0 + wc * 64 + ni * 8 + qc;
            *(float2*)(C + r0 * ldC + cb)       = make_float2(acc[mi][ni][0], acc[mi][ni][1]);
            *(float2*)(C + (r0 + 8) * ldC + cb) = make_float2(acc[mi][ni][2], acc[mi][ni][3]);
        }
    }
}

// ---------------- phi via HMMA: f = Q@omega (K=64), fused norm+exp ----------------
// block 128 thr (4 warps); grid (NROWS/128, 16) where y = qk*8 + h.
__global__ __launch_bounds__(128) void phi_mma(
    const float* __restrict__ Y, const __half* __restrict__ omT,
    float* __restrict__ Qphi, float* __restrict__ Kphi) {
    __shared__ __align__(16) __half At[128 * 72];
    __shared__ __align__(16) __half Bt[64 * 72];
    __shared__ float rowss[128];
    const int tid = threadIdx.x, lane = tid & 31, wid = tid >> 5;
    const int qk = blockIdx.y >> 3, h = blockIdx.y & 7;
    const long r0 = (long)blockIdx.x * 128;

    // omega^T tile [m][d] fp16
    const __half* om = omT + qk * 4096;
#pragma unroll
    for (int i = 0; i < 4; i++) {              // 512 slots of 8 halves
        int f = tid + i * 128; int m = f >> 3, c8 = f & 7;
        *(uint4*)&Bt[m * 72 + c8 * 8] = *(const uint4*)(om + m * 64 + c8 * 8);
    }

    // Q/K rows: fp32 -> fp16 tile + row sumsq (half-warp owns one row per iter)
    const float* src = Y + r0 * NC1 + qk * 512 + h * 64;
#pragma unroll
    for (int i = 0; i < 16; i++) {
        int idx = tid + i * 128;               // 2048 float4 slots: 128 rows x 16
        int r = idx >> 4, c4 = idx & 15;
        float4 v = *(const float4*)(src + (long)r * NC1 + c4 * 4);
        float s4 = v.x * v.x + v.y * v.y + v.z * v.z + v.w * v.w;
#pragma unroll
        for (int m = 8; m >= 1; m >>= 1)
            s4 += __shfl_xor_sync(0xffffffffu, s4, m, 16);
        if ((tid & 15) == 0) rowss[r] = s4;
        __half2 h0 = __floats2half2_rn(v.x, v.y);
        __half2 h1 = __floats2half2_rn(v.z, v.w);
        *(__half2*)&At[r * 72 + c4 * 4]     = h0;
        *(__half2*)&At[r * 72 + c4 * 4 + 2] = h1;
    }
    __syncthreads();

    const uint32_t AB = smem_u32(At), BB = smem_u32(Bt);
    const uint32_t aRow = (uint32_t)(wid * 32 + (lane & 15)) * ROWB;
    const uint32_t aCol = (uint32_t)((lane >> 4) * 8) * 2;
    const uint32_t bRow = (uint32_t)((lane & 7) + ((lane >> 4) & 1) * 8) * ROWB;
    const uint32_t bCol = (uint32_t)(((lane >> 3) & 1) * 8) * 2;

    float acc[2][8][4];
#pragma unroll
    for (int i = 0; i < 2; i++)
#pragma unroll
        for (int j = 0; j < 8; j++)
#pragma unroll
            for (int t = 0; t < 4; t++) acc[i][j][t] = 0.f;

#pragma unroll
    for (int kk = 0; kk < HD; kk += 16) {
        uint32_t af[2][4], bf[8][2];
#pragma unroll
        for (int np = 0; np < 4; np++) {
            uint32_t off = bRow + (uint32_t)(np * 16) * ROWB + kk * 2 + bCol;
            LDSM4(bf[2*np][0], bf[2*np][1], bf[2*np+1][0], bf[2*np+1][1], BB + off);
        }
#pragma unroll
        for (int mi = 0; mi < 2; mi++) {
            uint32_t off = aRow + (uint32_t)(mi * 16) * ROWB + kk * 2 + aCol;
            LDSM4(af[mi][0], af[mi][1], af[mi][2], af[mi][3], AB + off);
        }
#pragma unroll
        for (int mi = 0; mi < 2; mi++)
#pragma unroll
            for (int ni = 0; ni < 8; ni++)
                mma16816(acc[mi][ni], af[mi], bf[ni]);
    }

    const int qr = lane >> 2, qc = (lane & 3) * 2;
    const int b = (int)(r0 >> 14);
    const int sbase = (int)(r0 & 16383);
    float* dst = (qk == 0 ? Qphi : Kphi) + ((long)(b * HEADS + h) * SEQ) * MF;
#pragma unroll
    for (int mi = 0; mi < 2; mi++) {
        int ra = wid * 32 + mi * 16 + qr;
        float nt0 = fmaxf(expf(-0.5f * rowss[ra]),     1e-8f);
        float nt1 = fmaxf(expf(-0.5f * rowss[ra + 8]), 1e-8f);
        long o0 = (long)(sbase + ra) * MF;
        long o1 = (long)(sbase + ra + 8) * MF;
#pragma unroll
        for (int ni = 0; ni < 8; ni++) {
            int cb = ni * 8 + qc;
            dst[o0 + cb]     = nt0 * expf(fminf(acc[mi][ni][0], 50.0f));
            dst[o0 + cb + 1] = nt0 * expf(fminf(acc[mi][ni][1], 50.0f));
            dst[o1 + cb]     = nt1 * expf(fminf(acc[mi][ni][2], 50.0f));
            dst[o1 + cb + 1] = nt1 * expf(fminf(acc[mi][ni][3], 50.0f));
        }
    }
}

// ---------------- KV partials (V read from Y section) ----------------
__global__ __launch_bounds__(256) void kv_partial(
    const float* __restrict__ Kphi, const float* __restrict__ Y,
    float* __restrict__ KVp, float* __restrict__ Konesp) {
    __shared__ float Ks[32][MF];
    __shared__ float Vs[32][HD];
    const int tid = threadIdx.x;
    const int bh = blockIdx.y, part = blockIdx.x;
    const int b = bh / HEADS, h = bh % HEADS;
    const int s0 = part * SCHUNK;
    const int tr = (tid >> 4) * 4, tc = (tid & 15) * 4;
    float acc[4][4];
#pragma unroll
    for (int i = 0; i < 4; i++)
#pragma unroll
        for (int j = 0; j < 4; j++) acc[i][j] = 0.f;
    float kon = 0.f;

    for (int ss = 0; ss < SCHUNK; ss += 32) {
#pragma unroll
        for (int i = 0; i < 2; i++) {
            int f = tid + i * 256;
            int r = f >> 4, c = (f & 15) * 4;
            long s = (long)s0 + ss + r;
            *reinterpret_cast<float4*>(&Ks[r][c]) =
                *reinterpret_cast<const float4*>(Kphi + ((long)bh * SEQ + s) * MF + c);
            *reinterpret_cast<float4*>(&Vs[r][c]) =
                *reinterpret_cast<const float4*>(Y + ((long)b * SEQ + s) * NC1 + 1024 + h * HD + c);
        }
        __syncthreads();
#pragma unroll
        for (int k = 0; k < 32; k++) {
            float a[4], bb[4];
            *reinterpret_cast<float4*>(a)  = *reinterpret_cast<const float4*>(&Ks[k][tr]);
            *reinterpret_cast<float4*>(bb) = *reinterpret_cast<const float4*>(&Vs[k][tc]);
#pragma unroll
            for (int i = 0; i < 4; i++)
#pragma unroll
                for (int j = 0; j < 4; j++)
                    acc[i][j] = fmaf(a[i], bb[j], acc[i][j]);
        }
        if (tid < MF) {
#pragma unroll
            for (int k = 0; k < 32; k++) kon += Ks[k][tid];
        }
        __syncthreads();
    }
    float* dst = KVp + ((long)bh * NCHUNK + part) * (MF * HD);
#pragma unroll
    for (int i = 0; i < 4; i++) {
        float4 v = make_float4(acc[i][0], acc[i][1], acc[i][2], acc[i][3]);
        *reinterpret_cast<float4*>(dst + (tr + i) * HD + tc) = v;
    }
    if (tid < MF) Konesp[((long)bh * NCHUNK + part) * MF + tid] = kon;
}

__global__ __launch_bounds__(256) void kv_reduce(
    const float* __restrict__ KVp, const float* __restrict__ Konesp,
    float* __restrict__ KV, float* __restrict__ Kones) {
    const int bh = blockIdx.x, tid = threadIdx.x;
    for (int idx = tid; idx < MF * HD; idx += 256) {
        float s = 0.f;
#pragma unroll
        for (int p = 0; p < NCHUNK; p++)
            s += KVp[((long)bh * NCHUNK + p) * (MF * HD) + idx];
        KV[bh * MF * HD + idx] = s;
    }
    if (tid < MF) {
        float s = 0.f;
#pragma unroll
        for (int p = 0; p < NCHUNK; p++)
            s += Konesp[((long)bh * NCHUNK + p) * MF + tid];
        Kones[bh * MF + tid] = s;
    }
}

// ---------------- attn = (Qphi@KV)/(Qphi@Kones), written as fp16 ----------------
__global__ __launch_bounds__(256) void qkv_attn(
    const float* __restrict__ Qphi, const float* __restrict__ KV,
    const float* __restrict__ Kones, __half* __restrict__ Ah) {
    __shared__ float KVs[MF][HD];
    __shared__ float ko[MF];
    __shared__ float q[4][MF];
    const int tid = threadIdx.x;
    const int bh = blockIdx.y;
    const int b = bh / HEADS, h = bh % HEADS;
    const int s0 = blockIdx.x * 256;
#pragma unroll
    for (int i = 0; i < 4; i++) {
        int f = tid + i * 256;
        int m = f >> 4, c = (f & 15) * 4;
        *reinterpret_cast<float4*>(&KVs[m][c]) =
            *reinterpret_cast<const float4*>(KV + (long)bh * MF * HD + m * HD + c);
    }
    if (tid < MF) ko[tid] = Kones[bh * MF + tid];
    __syncthreads();

    const int sub = tid >> 6, t = tid & 63;
    for (int ss = 0; ss < 256; ss += 4) {
        int s = s0 + ss + sub;
        q[sub][t] = Qphi[((long)bh * SEQ + s) * MF + t];
        __syncthreads();
        float num = 0.f, den = 0.f;
#pragma unroll
        for (int m = 0; m < MF; m++) {
            float qm = q[sub][m];
            den = fmaf(qm, ko[m], den);
            num = fmaf(qm, KVs[m][t], num);
        }
        Ah[((long)b * SEQ + s) * EMB + h * HD + t] = __float2half_rn(num / den);
        __syncthreads();
    }
}

// ---------------- launch ----------------
extern "C" void kernel_launch(void* const* d_in, const int* in_sizes, int n_in,
                              void* d_out, int out_size) {
    const float* x   = (const float*)d_in[0];
    const float* Wq  = (const float*)d_in[1];
    const float* Wk  = (const float*)d_in[2];
    const float* Wv  = (const float*)d_in[3];
    const float* Wo  = (const float*)d_in[4];
    const float* omq = (const float*)d_in[5];
    const float* omk = (const float*)d_in[6];
    float* out = (float*)d_out;

    __half *pXh, *pWh1, *pWl1, *pWh2, *pWl2, *pOmT;
    float *pWeff, *pY, *pQphi, *pKphi, *pKVp, *pKonesp, *pKV, *pKones;
    cudaGetSymbolAddress((void**)&pXh,    g_Xh);
    cudaGetSymbolAddress((void**)&pWeff,  g_Weff);
    cudaGetSymbolAddress((void**)&pWh1,   g_Wh1);
    cudaGetSymbolAddress((void**)&pWl1,   g_Wl1);
    cudaGetSymbolAddress((void**)&pWh2,   g_Wh2);
    cudaGetSymbolAddress((void**)&pWl2,   g_Wl2);
    cudaGetSymbolAddress((void**)&pOmT,   g_omT);
    cudaGetSymbolAddress((void**)&pY,     g_Y);
    cudaGetSymbolAddress((void**)&pQphi,  g_Qphi);
    cudaGetSymbolAddress((void**)&pKphi,  g_Kphi);
    cudaGetSymbolAddress((void**)&pKVp,   g_KVp);
    cudaGetSymbolAddress((void**)&pKonesp,g_Konesp);
    cudaGetSymbolAddress((void**)&pKV,    g_KV);
    cudaGetSymbolAddress((void**)&pKones, g_Kones);

    cudaFuncSetAttribute(gemm_mma2, cudaFuncAttributeMaxDynamicSharedMemorySize, SMEMSZ);

    cvt_x<<<(NROWS * EMB) / 256, 256>>>(x, pXh);
    cvt_omega<<<(2 * HD * MF) / 256, 256>>>(omq, omk, pOmT);
    prep_weff<<<dim3(NC1 / 256, EMB), 256>>>(Wq, Wk, Wv, pWeff);
    tsplit<<<dim3(NC1 / 32, EMB / 32), dim3(32, 8)>>>(pWeff, NC1, pWh1, pWl1);
    tsplit<<<dim3(EMB / 32, EMB / 32), dim3(32, 8)>>>(Wo, EMB, pWh2, pWl2);

    gemm_mma2<<<dim3(NC1 / BN, NROWS / BM), 256, SMEMSZ>>>(pXh, pWh1, pWl1, pY, NC1);

    phi_mma<<<dim3(NROWS / 128, 16), 128>>>(pY, pOmT, pQphi, pKphi);

    kv_partial<<<dim3(NCHUNK, BH), 256>>>(pKphi, pY, pKVp, pKonesp);
    kv_reduce<<<BH, 256>>>(pKVp, pKonesp, pKV, pKones);
    // g_Xh dead after gemm1 -> reuse for attn fp16
    qkv_attn<<<dim3(SEQ / 256, BH), 256>>>(pQphi, pKV, pKones, pXh);

    gemm_mma2<<<dim3(EMB / BN, NROWS / BM), 256, SMEMSZ>>>(pXh, pWh2, pWl2, out, EMB);
}

// round 13
// speedup vs baseline: 2.9391x; 1.1599x over previous
#include <cuda_runtime.h>
#include <cuda_fp16.h>
#include <math.h>
#include <stdint.h>

#define BATCH 2
#define SEQ   16384
#define EMB   512
#define HEADS 8
#define HD    64
#define MF    64
#define NROWS 32768          // BATCH*SEQ
#define BH    16
#define NC1   1536           // [Q|K|V] columns
#define NCHUNK 16
#define SCHUNK 1024

// ---------------- device scratch ----------------
__device__ __align__(1024) __half g_Xh[(long)NROWS * EMB];
__device__ __align__(1024) float  g_Weff[EMB * NC1];
__device__ __align__(1024) __half g_Wh1[(long)NC1 * EMB];
__device__ __align__(1024) __half g_Wl1[(long)NC1 * EMB];
__device__ __align__(1024) __half g_Wh2[EMB * EMB];
__device__ __align__(1024) __half g_Wl2[EMB * EMB];
__device__ __align__(1024) __half g_omT[2 * HD * MF];   // fp16 omega^T [qk][m][d]
__device__ __align__(1024) float  g_Y[(long)NROWS * NC1];
__device__ __align__(1024) float  g_Qphi[(long)BH * SEQ * MF];
__device__ __align__(1024) float  g_Kphi[(long)BH * SEQ * MF];
__device__ __align__(1024) float  g_KVp[BH * NCHUNK * MF * HD];
__device__ __align__(1024) float  g_Konesp[BH * NCHUNK * MF];
__device__ __align__(1024) float  g_KV[BH * MF * HD];
__device__ __align__(1024) float  g_Kones[BH * MF];

// ---------------- helpers ----------------
__device__ __forceinline__ uint32_t smem_u32(const void* p) {
    uint32_t a;
    asm("{ .reg .u64 t; cvta.to.shared.u64 t, %1; cvt.u32.u64 %0, t; }" : "=r"(a) : "l"(p));
    return a;
}
#define CP16(dst, src)   asm volatile("cp.async.cg.shared.global [%0], [%1], 16;" :: "r"(dst), "l"(src))
#define CP_COMMIT()      asm volatile("cp.async.commit_group;" ::: "memory")
#define CP_WAIT1()       asm volatile("cp.async.wait_group 1;" ::: "memory")
#define CP_WAIT0()       asm volatile("cp.async.wait_group 0;" ::: "memory")
#define LDSM4(r0,r1,r2,r3,addr) \
    asm volatile("ldmatrix.sync.aligned.m8n8.x4.shared.b16 {%0,%1,%2,%3}, [%4];" \
        : "=r"(r0), "=r"(r1), "=r"(r2), "=r"(r3) : "r"(addr))

__device__ __forceinline__ void mma16816(float* c, const uint32_t* a, const uint32_t* b) {
    asm volatile(
        "mma.sync.aligned.m16n8k16.row.col.f32.f16.f16.f32 "
        "{%0,%1,%2,%3}, {%4,%5,%6,%7}, {%8,%9}, {%0,%1,%2,%3};"
        : "+f"(c[0]), "+f"(c[1]), "+f"(c[2]), "+f"(c[3])
        : "r"(a[0]), "r"(a[1]), "r"(a[2]), "r"(a[3]), "r"(b[0]), "r"(b[1]));
}

// ---------------- prep: x -> fp16 ----------------
__global__ __launch_bounds__(256) void cvt_x(const float* __restrict__ x,
                                             __half* __restrict__ oh) {
    long idx = (long)blockIdx.x * 256 + threadIdx.x;
    oh[idx] = __float2half_rn(x[idx]);
}

// ---------------- prep: omega [d][m] fp32 -> omega^T [m][d] fp16 ----------------
__global__ __launch_bounds__(256) void cvt_omega(const float* __restrict__ omq,
                                                 const float* __restrict__ omk,
                                                 __half* __restrict__ omT) {
    int i = blockIdx.x * 256 + threadIdx.x;     // over 2*4096
    int qk = i >> 12, e = i & 4095;
    int m = e >> 6, d = e & 63;
    const float* src = qk ? omk : omq;
    omT[qk * 4096 + m * 64 + d] = __float2half_rn(src[d * 64 + m]);
}

// ---------------- prep: W_eff[k][n] = [s*Wq | s*Wk | Wv] ----------------
__global__ __launch_bounds__(256) void prep_weff(
    const float* __restrict__ Wq, const float* __restrict__ Wk,
    const float* __restrict__ Wv, float* __restrict__ Weff) {
    const int k = blockIdx.y;
    const int n = blockIdx.x * 256 + threadIdx.x;
    float r;
    if (n < 512)       r = Wq[k * 512 + n] * 0.125f;
    else if (n < 1024) r = Wk[k * 512 + n - 512] * 0.125f;
    else               r = Wv[k * 512 + n - 1024];
    Weff[k * NC1 + n] = r;
}

// ---------------- prep: transpose + split W [512 x N] -> hi/lo [N x 512] ----------------
__global__ void tsplit(const float* __restrict__ W, int N,
                       __half* __restrict__ Whi, __half* __restrict__ Wlo) {
    __shared__ float t[32][33];
    const int k0 = blockIdx.y * 32, n0 = blockIdx.x * 32;
#pragma unroll
    for (int i = 0; i < 4; i++) {
        int r = threadIdx.y + i * 8;
        t[r][threadIdx.x] = W[(k0 + r) * N + n0 + threadIdx.x];
    }
    __syncthreads();
#pragma unroll
    for (int i = 0; i < 4; i++) {
        int n = threadIdx.y + i * 8, k = threadIdx.x;
        float v = t[k][n];
        __half hi = __float2half_rn(v);
        __half lo = __float2half_rn(v - __half2float(hi));
        long ob = (long)(n0 + n) * EMB + k0 + k;
        Whi[ob] = hi; Wlo[ob] = lo;
    }
}

// ---------------- shared GEMM geometry (R9/R10-proven skeleton) ----------------
#define BM 128
#define BN 256
#define BK 64
#define ROWB 144                       // padded row bytes (72 halves)
#define A_TILE (BM * ROWB)             // 18432
#define B_TILE (BN * ROWB)             // 36864
#define KCH (EMB / BK)                 // 8
// 2-term variant (gemm2)
#define STAGE2  (A_TILE + 2 * B_TILE)  // 92160
#define SMEMSZ2 (2 * STAGE2)           // 184320
// 1-term variant (gemm1)
#define STAGE1  (A_TILE + B_TILE)      // 55296
#define SMEMSZ1 (2 * STAGE1)           // 110592

// ---------------- 1-term GEMM: C = Ah@Bh^T (gemm1: projections) ----------------
__global__ void __launch_bounds__(256, 1) gemm_mma1(
    const __half* __restrict__ Ah, const __half* __restrict__ Bhi,
    float* __restrict__ C, int ldC) {
    extern __shared__ __align__(16) char smraw[];
    const uint32_t sb = smem_u32(smraw);
    const int tid = threadIdx.x, wid = tid >> 5, lane = tid & 31;
    const int wr = wid >> 2, wc = wid & 3;
    const long row0 = (long)blockIdx.y * BM;
    const int  col0 = blockIdx.x * BN;

    const __half* Ag  = Ah  + row0 * EMB;
    const __half* Bgh = Bhi + (long)col0 * EMB;

    auto load_tiles = [&](int ch, int s) {
        uint32_t base = sb + s * STAGE1;
#pragma unroll
        for (int i = 0; i < 4; i++) {
            int f = tid + i * 256; int r = f >> 3, c = f & 7;
            CP16(base + r * ROWB + c * 16, Ag + ch * BK + (long)r * EMB + c * 8);
        }
#pragma unroll
        for (int i = 0; i < 8; i++) {
            int f = tid + i * 256; int r = f >> 3, c = f & 7;
            CP16(base + A_TILE + r * ROWB + c * 16, Bgh + ch * BK + (long)r * EMB + c * 8);
        }
    };

    float acc[4][8][4];
#pragma unroll
    for (int i = 0; i < 4; i++)
#pragma unroll
        for (int j = 0; j < 8; j++)
#pragma unroll
            for (int t = 0; t < 4; t++) acc[i][j][t] = 0.f;

    load_tiles(0, 0);
    CP_COMMIT();

    const uint32_t aRow = (uint32_t)(wr * 64 + (lane & 15)) * ROWB;
    const uint32_t aCol = (uint32_t)((lane >> 4) * 8) * 2;
    const uint32_t bRow = (uint32_t)(wc * 64 + (lane & 7) + ((lane >> 4) & 1) * 8) * ROWB;
    const uint32_t bCol = (uint32_t)(((lane >> 3) & 1) * 8) * 2;

    for (int ch = 0; ch < KCH; ch++) {
        const int st = ch & 1;
        if (ch + 1 < KCH) { load_tiles(ch + 1, st ^ 1); CP_COMMIT(); CP_WAIT1(); }
        else              { CP_WAIT0(); }
        __syncthreads();

        const uint32_t stB = sb + st * STAGE1;
        const uint32_t AB = stB, BhB = stB + A_TILE;
#pragma unroll
        for (int kk = 0; kk < BK; kk += 16) {
            uint32_t af[4][4], bh[8][2];
#pragma unroll
            for (int np = 0; np < 4; np++) {
                uint32_t off = bRow + (uint32_t)(np * 16) * ROWB + kk * 2 + bCol;
                LDSM4(bh[2*np][0], bh[2*np][1], bh[2*np+1][0], bh[2*np+1][1], BhB + off);
            }
#pragma unroll
            for (int mi = 0; mi < 4; mi++) {
                uint32_t off = aRow + (uint32_t)(mi * 16) * ROWB + kk * 2 + aCol;
                LDSM4(af[mi][0], af[mi][1], af[mi][2], af[mi][3], AB + off);
            }
#pragma unroll
            for (int mi = 0; mi < 4; mi++)
#pragma unroll
                for (int ni = 0; ni < 8; ni++)
                    mma16816(acc[mi][ni], af[mi], bh[ni]);
        }
        __syncthreads();
    }

    const int qr = lane >> 2;
    const int qc = (lane & 3) * 2;
#pragma unroll
    for (int mi = 0; mi < 4; mi++) {
        long r0 = row0 + wr * 64 + mi * 16 + qr;
#pragma unroll
        for (int ni = 0; ni < 8; ni++) {
            int cb = col0 + wc * 64 + ni * 8 + qc;
            *(float2*)(C + r0 * ldC + cb)       = make_float2(acc[mi][ni][0], acc[mi][ni][1]);
            *(float2*)(C + (r0 + 8) * ldC + cb) = make_float2(acc[mi][ni][2], acc[mi][ni][3]);
        }
    }
}

// ---------------- 2-term GEMM: C = Ah@Bh^T + Ah@Bl^T (gemm2: output proj) ----------------
__global__ void __launch_bounds__(256, 1) gemm_mma2(
    const __half* __restrict__ Ah,
    const __half* __restrict__ Bhi, const __half* __restrict__ Blo,
    float* __restrict__ C, int ldC) {
    extern __shared__ __align__(16) char smraw[];
    const uint32_t sb = smem_u32(smraw);
    const int tid = threadIdx.x, wid = tid >> 5, lane = tid & 31;
    const int wr = wid >> 2, wc = wid & 3;
    const long row0 = (long)blockIdx.y * BM;
    const int  col0 = blockIdx.x * BN;

    const __half* Ag  = Ah  + row0 * EMB;
    const __half* Bgh = Bhi + (long)col0 * EMB;
    const __half* Bgl = Blo + (long)col0 * EMB;

    auto load_tiles = [&](int ch, int s) {
        uint32_t base = sb + s * STAGE2;
#pragma unroll
        for (int i = 0; i < 4; i++) {
            int f = tid + i * 256; int r = f >> 3, c = f & 7;
            CP16(base + r * ROWB + c * 16, Ag + ch * BK + (long)r * EMB + c * 8);
        }
#pragma unroll
        for (int i = 0; i < 8; i++) {
            int f = tid + i * 256; int r = f >> 3, c = f & 7;
            CP16(base + A_TILE + r * ROWB + c * 16, Bgh + ch * BK + (long)r * EMB + c * 8);
        }
#pragma unroll
        for (int i = 0; i < 8; i++) {
            int f = tid + i * 256; int r = f >> 3, c = f & 7;
            CP16(base + A_TILE + B_TILE + r * ROWB + c * 16, Bgl + ch * BK + (long)r * EMB + c * 8);
        }
    };

    float acc[4][8][4];
#pragma unroll
    for (int i = 0; i < 4; i++)
#pragma unroll
        for (int j = 0; j < 8; j++)
#pragma unroll
            for (int t = 0; t < 4; t++) acc[i][j][t] = 0.f;

    load_tiles(0, 0);
    CP_COMMIT();

    const uint32_t aRow = (uint32_t)(wr * 64 + (lane & 15)) * ROWB;
    const uint32_t aCol = (uint32_t)((lane >> 4) * 8) * 2;
    const uint32_t bRow = (uint32_t)(wc * 64 + (lane & 7) + ((lane >> 4) & 1) * 8) * ROWB;
    const uint32_t bCol = (uint32_t)(((lane >> 3) & 1) * 8) * 2;

    for (int ch = 0; ch < KCH; ch++) {
        const int st = ch & 1;
        if (ch + 1 < KCH) { load_tiles(ch + 1, st ^ 1); CP_COMMIT(); CP_WAIT1(); }
        else              { CP_WAIT0(); }
        __syncthreads();

        const uint32_t stB = sb + st * STAGE2;
        const uint32_t AB = stB, BhB = stB + A_TILE, BlB = BhB + B_TILE;
#pragma unroll
        for (int kk = 0; kk < BK; kk += 16) {
            uint32_t af[4][4], bh[8][2], bl[8][2];
#pragma unroll
            for (int np = 0; np < 4; np++) {
                uint32_t off = bRow + (uint32_t)(np * 16) * ROWB + kk * 2 + bCol;
                LDSM4(bh[2*np][0], bh[2*np][1], bh[2*np+1][0], bh[2*np+1][1], BhB + off);
                LDSM4(bl[2*np][0], bl[2*np][1], bl[2*np+1][0], bl[2*np+1][1], BlB + off);
            }
#pragma unroll
            for (int mi = 0; mi < 4; mi++) {
                uint32_t off = aRow + (uint32_t)(mi * 16) * ROWB + kk * 2 + aCol;
                LDSM4(af[mi][0], af[mi][1], af[mi][2], af[mi][3], AB + off);
            }
#pragma unroll
            for (int mi = 0; mi < 4; mi++)
#pragma unroll
                for (int ni = 0; ni < 8; ni++)
                    mma16816(acc[mi][ni], af[mi], bh[ni]);
#pragma unroll
            for (int mi = 0; mi < 4; mi++)
#pragma unroll
                for (int ni = 0; ni < 8; ni++)
                    mma16816(acc[mi][ni], af[mi], bl[ni]);
        }
        __syncthreads();
    }

    const int qr = lane >> 2;
    const int qc = (lane & 3) * 2;
#pragma unroll
    for (int mi = 0; mi < 4; mi++) {
        long r0 = row0 + wr * 64 + mi * 16 + qr;
#pragma unroll
        for (int ni = 0; ni < 8; ni++) {
            int cb = col0 + wc * 64 + ni * 8 + qc;
            *(float2*)(C + r0 * ldC + cb)       = make_float2(acc[mi][ni][0], acc[mi][ni][1]);
            *(float2*)(C + (r0 + 8) * ldC + cb) = make_float2(acc[mi][ni][2], acc[mi][ni][3]);
        }
    }
}

// ---------------- phi via HMMA: f = Q@omega (K=64), fused norm+exp ----------------
__global__ __launch_bounds__(128) void phi_mma(
    const float* __restrict__ Y, const __half* __restrict__ omT,
    float* __restrict__ Qphi, float* __restrict__ Kphi) {
    __shared__ __align__(16) __half At[128 * 72];
    __shared__ __align__(16) __half Bt[64 * 72];
    __shared__ float rowss[128];
    const int tid = threadIdx.x, lane = tid & 31, wid = tid >> 5;
    const int qk = blockIdx.y >> 3, h = blockIdx.y & 7;
    const long r0 = (long)blockIdx.x * 128;

    const __half* om = omT + qk * 4096;
#pragma unroll
    for (int i = 0; i < 4; i++) {
        int f = tid + i * 128; int m = f >> 3, c8 = f & 7;
        *(uint4*)&Bt[m * 72 + c8 * 8] = *(const uint4*)(om + m * 64 + c8 * 8);
    }

    const float* src = Y + r0 * NC1 + qk * 512 + h * 64;
#pragma unroll
    for (int i = 0; i < 16; i++) {
        int idx = tid + i * 128;
        int r = idx >> 4, c4 = idx & 15;
        float4 v = *(const float4*)(src + (long)r * NC1 + c4 * 4);
        float s4 = v.x * v.x + v.y * v.y + v.z * v.z + v.w * v.w;
#pragma unroll
        for (int m = 8; m >= 1; m >>= 1)
            s4 += __shfl_xor_sync(0xffffffffu, s4, m, 16);
        if ((tid & 15) == 0) rowss[r] = s4;
        __half2 h0 = __floats2half2_rn(v.x, v.y);
        __half2 h1 = __floats2half2_rn(v.z, v.w);
        *(__half2*)&At[r * 72 + c4 * 4]     = h0;
        *(__half2*)&At[r * 72 + c4 * 4 + 2] = h1;
    }
    __syncthreads();

    const uint32_t AB = smem_u32(At), BB = smem_u32(Bt);
    const uint32_t aRow = (uint32_t)(wid * 32 + (lane & 15)) * ROWB;
    const uint32_t aCol = (uint32_t)((lane >> 4) * 8) * 2;
    const uint32_t bRow = (uint32_t)((lane & 7) + ((lane >> 4) & 1) * 8) * ROWB;
    const uint32_t bCol = (uint32_t)(((lane >> 3) & 1) * 8) * 2;

    float acc[2][8][4];
#pragma unroll
    for (int i = 0; i < 2; i++)
#pragma unroll
        for (int j = 0; j < 8; j++)
#pragma unroll
            for (int t = 0; t < 4; t++) acc[i][j][t] = 0.f;

#pragma unroll
    for (int kk = 0; kk < HD; kk += 16) {
        uint32_t af[2][4], bf[8][2];
#pragma unroll
        for (int np = 0; np < 4; np++) {
            uint32_t off = bRow + (uint32_t)(np * 16) * ROWB + kk * 2 + bCol;
            LDSM4(bf[2*np][0], bf[2*np][1], bf[2*np+1][0], bf[2*np+1][1], BB + off);
        }
#pragma unroll
        for (int mi = 0; mi < 2; mi++) {
            uint32_t off = aRow + (uint32_t)(mi * 16) * ROWB + kk * 2 + aCol;
            LDSM4(af[mi][0], af[mi][1], af[mi][2], af[mi][3], AB + off);
        }
#pragma unroll
        for (int mi = 0; mi < 2; mi++)
#pragma unroll
            for (int ni = 0; ni < 8; ni++)
                mma16816(acc[mi][ni], af[mi], bf[ni]);
    }

    const int qr = lane >> 2, qc = (lane & 3) * 2;
    const int b = (int)(r0 >> 14);
    const int sbase = (int)(r0 & 16383);
    float* dst = (qk == 0 ? Qphi : Kphi) + ((long)(b * HEADS + h) * SEQ) * MF;
#pragma unroll
    for (int mi = 0; mi < 2; mi++) {
        int ra = wid * 32 + mi * 16 + qr;
        float nt0 = fmaxf(expf(-0.5f * rowss[ra]),     1e-8f);
        float nt1 = fmaxf(expf(-0.5f * rowss[ra + 8]), 1e-8f);
        long o0 = (long)(sbase + ra) * MF;
        long o1 = (long)(sbase + ra + 8) * MF;
#pragma unroll
        for (int ni = 0; ni < 8; ni++) {
            int cb = ni * 8 + qc;
            dst[o0 + cb]     = nt0 * expf(fminf(acc[mi][ni][0], 50.0f));
            dst[o0 + cb + 1] = nt0 * expf(fminf(acc[mi][ni][1], 50.0f));
            dst[o1 + cb]     = nt1 * expf(fminf(acc[mi][ni][2], 50.0f));
            dst[o1 + cb + 1] = nt1 * expf(fminf(acc[mi][ni][3], 50.0f));
        }
    }
}

// ---------------- KV partials (V read from Y section) ----------------
__global__ __launch_bounds__(256) void kv_partial(
    const float* __restrict__ Kphi, const float* __restrict__ Y,
    float* __restrict__ KVp, float* __restrict__ Konesp) {
    __shared__ float Ks[32][MF];
    __shared__ float Vs[32][HD];
    const int tid = threadIdx.x;
    const int bh = blockIdx.y, part = blockIdx.x;
    const int b = bh / HEADS, h = bh % HEADS;
    const int s0 = part * SCHUNK;
    const int tr = (tid >> 4) * 4, tc = (tid & 15) * 4;
    float acc[4][4];
#pragma unroll
    for (int i = 0; i < 4; i++)
#pragma unroll
        for (int j = 0; j < 4; j++) acc[i][j] = 0.f;
    float kon = 0.f;

    for (int ss = 0; ss < SCHUNK; ss += 32) {
#pragma unroll
        for (int i = 0; i < 2; i++) {
            int f = tid + i * 256;
            int r = f >> 4, c = (f & 15) * 4;
            long s = (long)s0 + ss + r;
            *reinterpret_cast<float4*>(&Ks[r][c]) =
                *reinterpret_cast<const float4*>(Kphi + ((long)bh * SEQ + s) * MF + c);
            *reinterpret_cast<float4*>(&Vs[r][c]) =
                *reinterpret_cast<const float4*>(Y + ((long)b * SEQ + s) * NC1 + 1024 + h * HD + c);
        }
        __syncthreads();
#pragma unroll
        for (int k = 0; k < 32; k++) {
            float a[4], bb[4];
            *reinterpret_cast<float4*>(a)  = *reinterpret_cast<const float4*>(&Ks[k][tr]);
            *reinterpret_cast<float4*>(bb) = *reinterpret_cast<const float4*>(&Vs[k][tc]);
#pragma unroll
            for (int i = 0; i < 4; i++)
#pragma unroll
                for (int j = 0; j < 4; j++)
                    acc[i][j] = fmaf(a[i], bb[j], acc[i][j]);
        }
        if (tid < MF) {
#pragma unroll
            for (int k = 0; k < 32; k++) kon += Ks[k][tid];
        }
        __syncthreads();
    }
    float* dst = KVp + ((long)bh * NCHUNK + part) * (MF * HD);
#pragma unroll
    for (int i = 0; i < 4; i++) {
        float4 v = make_float4(acc[i][0], acc[i][1], acc[i][2], acc[i][3]);
        *reinterpret_cast<float4*>(dst + (tr + i) * HD + tc) = v;
    }
    if (tid < MF) Konesp[((long)bh * NCHUNK + part) * MF + tid] = kon;
}

__global__ __launch_bounds__(256) void kv_reduce(
    const float* __restrict__ KVp, const float* __restrict__ Konesp,
    float* __restrict__ KV, float* __restrict__ Kones) {
    const int bh = blockIdx.x, tid = threadIdx.x;
    for (int idx = tid; idx < MF * HD; idx += 256) {
        float s = 0.f;
#pragma unroll
        for (int p = 0; p < NCHUNK; p++)
            s += KVp[((long)bh * NCHUNK + p) * (MF * HD) + idx];
        KV[bh * MF * HD + idx] = s;
    }
    if (tid < MF) {
        float s = 0.f;
#pragma unroll
        for (int p = 0; p < NCHUNK; p++)
            s += Konesp[((long)bh * NCHUNK + p) * MF + tid];
        Kones[bh * MF + tid] = s;
    }
}

// ---------------- attn = (Qphi@KV)/(Qphi@Kones), written as fp16 ----------------
__global__ __launch_bounds__(256) void qkv_attn(
    const float* __restrict__ Qphi, const float* __restrict__ KV,
    const float* __restrict__ Kones, __half* __restrict__ Ah) {
    __shared__ float KVs[MF][HD];
    __shared__ float ko[MF];
    __shared__ float q[4][MF];
    const int tid = threadIdx.x;
    const int bh = blockIdx.y;
    const int b = bh / HEADS, h = bh % HEADS;
    const int s0 = blockIdx.x * 256;
#pragma unroll
    for (int i = 0; i < 4; i++) {
        int f = tid + i * 256;
        int m = f >> 4, c = (f & 15) * 4;
        *reinterpret_cast<float4*>(&KVs[m][c]) =
            *reinterpret_cast<const float4*>(KV + (long)bh * MF * HD + m * HD + c);
    }
    if (tid < MF) ko[tid] = Kones[bh * MF + tid];
    __syncthreads();

    const int sub = tid >> 6, t = tid & 63;
    for (int ss = 0; ss < 256; ss += 4) {
        int s = s0 + ss + sub;
        q[sub][t] = Qphi[((long)bh * SEQ + s) * MF + t];
        __syncthreads();
        float num = 0.f, den = 0.f;
#pragma unroll
        for (int m = 0; m < MF; m++) {
            float qm = q[sub][m];
            den = fmaf(qm, ko[m], den);
            num = fmaf(qm, KVs[m][t], num);
        }
        Ah[((long)b * SEQ + s) * EMB + h * HD + t] = __float2half_rn(num / den);
        __syncthreads();
    }
}

// ---------------- launch ----------------
extern "C" void kernel_launch(void* const* d_in, const int* in_sizes, int n_in,
                              void* d_out, int out_size) {
    const float* x   = (const float*)d_in[0];
    const float* Wq  = (const float*)d_in[1];
    const float* Wk  = (const float*)d_in[2];
    const float* Wv  = (const float*)d_in[3];
    const float* Wo  = (const float*)d_in[4];
    const float* omq = (const float*)d_in[5];
    const float* omk = (const float*)d_in[6];
    float* out = (float*)d_out;

    __half *pXh, *pWh1, *pWl1, *pWh2, *pWl2, *pOmT;
    float *pWeff, *pY, *pQphi, *pKphi, *pKVp, *pKonesp, *pKV, *pKones;
    cudaGetSymbolAddress((void**)&pXh,    g_Xh);
    cudaGetSymbolAddress((void**)&pWeff,  g_Weff);
    cudaGetSymbolAddress((void**)&pWh1,   g_Wh1);
    cudaGetSymbolAddress((void**)&pWl1,   g_Wl1);
    cudaGetSymbolAddress((void**)&pWh2,   g_Wh2);
    cudaGetSymbolAddress((void**)&pWl2,   g_Wl2);
    cudaGetSymbolAddress((void**)&pOmT,   g_omT);
    cudaGetSymbolAddress((void**)&pY,     g_Y);
    cudaGetSymbolAddress((void**)&pQphi,  g_Qphi);
    cudaGetSymbolAddress((void**)&pKphi,  g_Kphi);
    cudaGetSymbolAddress((void**)&pKVp,   g_KVp);
    cudaGetSymbolAddress((void**)&pKonesp,g_Konesp);
    cudaGetSymbolAddress((void**)&pKV,    g_KV);
    cudaGetSymbolAddress((void**)&pKones, g_Kones);

    cudaFuncSetAttribute(gemm_mma1, cudaFuncAttributeMaxDynamicSharedMemorySize, SMEMSZ1);
    cudaFuncSetAttribute(gemm_mma2, cudaFuncAttributeMaxDynamicSharedMemorySize, SMEMSZ2);

    cvt_x<<<(NROWS * EMB) / 256, 256>>>(x, pXh);
    cvt_omega<<<(2 * HD * MF) / 256, 256>>>(omq, omk, pOmT);
    prep_weff<<<dim3(NC1 / 256, EMB), 256>>>(Wq, Wk, Wv, pWeff);
    tsplit<<<dim3(NC1 / 32, EMB / 32), dim3(32, 8)>>>(pWeff, NC1, pWh1, pWl1);
    tsplit<<<dim3(EMB / 32, EMB / 32), dim3(32, 8)>>>(Wo, EMB, pWh2, pWl2);

    gemm_mma1<<<dim3(NC1 / BN, NROWS / BM), 256, SMEMSZ1>>>(pXh, pWh1, pY, NC1);

    phi_mma<<<dim3(NROWS / 128, 16), 128>>>(pY, pOmT, pQphi, pKphi);

    kv_partial<<<dim3(NCHUNK, BH), 256>>>(pKphi, pY, pKVp, pKonesp);
    kv_reduce<<<BH, 256>>>(pKVp, pKonesp, pKV, pKones);
    // g_Xh dead after gemm1 -> reuse for attn fp16
    qkv_attn<<<dim3(SEQ / 256, BH), 256>>>(pQphi, pKV, pKones, pXh);

    gemm_mma2<<<dim3(EMB / BN, NROWS / BM), 256, SMEMSZ2>>>(pXh, pWh2, pWl2, out, EMB);
}

// round 15
// speedup vs baseline: 3.1722x; 1.0793x over previous
#include <cuda_runtime.h>
#include <cuda_fp16.h>
#include <math.h>
#include <stdint.h>

#define BATCH 2
#define SEQ   16384
#define EMB   512
#define HEADS 8
#define HD    64
#define MF    64
#define NROWS 32768          // BATCH*SEQ
#define BH    16
#define NC1   1536           // [Q|K|V] columns
#define NCHUNK 16
#define SCHUNK 1024

// ---------------- device scratch ----------------
__device__ __align__(1024) __half g_Xh[(long)NROWS * EMB];
__device__ __align__(1024) float  g_Weff[EMB * NC1];
__device__ __align__(1024) __half g_Wh1[(long)NC1 * EMB];
__device__ __align__(1024) __half g_Wl1[(long)NC1 * EMB];
__device__ __align__(1024) __half g_Wh2[EMB * EMB];
__device__ __align__(1024) __half g_Wl2[EMB * EMB];
__device__ __align__(1024) __half g_omT[2 * HD * MF];   // fp16 omega^T [qk][m][d]
__device__ __align__(1024) __half g_Yh[(long)NROWS * NC1];   // fp16 projections
__device__ __align__(1024) float  g_Qphi[(long)BH * SEQ * MF];
__device__ __align__(1024) float  g_Kphi[(long)BH * SEQ * MF];
__device__ __align__(1024) float  g_KVp[BH * NCHUNK * MF * HD];
__device__ __align__(1024) float  g_Konesp[BH * NCHUNK * MF];
__device__ __align__(1024) float  g_KV[BH * MF * HD];
__device__ __align__(1024) float  g_Kones[BH * MF];

// ---------------- helpers ----------------
__device__ __forceinline__ uint32_t smem_u32(const void* p) {
    uint32_t a;
    asm("{ .reg .u64 t; cvta.to.shared.u64 t, %1; cvt.u32.u64 %0, t; }" : "=r"(a) : "l"(p));
    return a;
}
#define CP16(dst, src)   asm volatile("cp.async.cg.shared.global [%0], [%1], 16;" :: "r"(dst), "l"(src))
#define CP_COMMIT()      asm volatile("cp.async.commit_group;" ::: "memory")
#define CP_WAIT1()       asm volatile("cp.async.wait_group 1;" ::: "memory")
#define CP_WAIT0()       asm volatile("cp.async.wait_group 0;" ::: "memory")
#define LDSM4(r0,r1,r2,r3,addr) \
    asm volatile("ldmatrix.sync.aligned.m8n8.x4.shared.b16 {%0,%1,%2,%3}, [%4];" \
        : "=r"(r0), "=r"(r1), "=r"(r2), "=r"(r3) : "r"(addr))

__device__ __forceinline__ void mma16816(float* c, const uint32_t* a, const uint32_t* b) {
    asm volatile(
        "mma.sync.aligned.m16n8k16.row.col.f32.f16.f16.f32 "
        "{%0,%1,%2,%3}, {%4,%5,%6,%7}, {%8,%9}, {%0,%1,%2,%3};"
        : "+f"(c[0]), "+f"(c[1]), "+f"(c[2]), "+f"(c[3])
        : "r"(a[0]), "r"(a[1]), "r"(a[2]), "r"(a[3]), "r"(b[0]), "r"(b[1]));
}

// ---------------- prep: x -> fp16 ----------------
__global__ __launch_bounds__(256) void cvt_x(const float* __restrict__ x,
                                             __half* __restrict__ oh) {
    long idx = (long)blockIdx.x * 256 + threadIdx.x;
    oh[idx] = __float2half_rn(x[idx]);
}

// ---------------- prep: omega [d][m] fp32 -> omega^T [m][d] fp16 ----------------
__global__ __launch_bounds__(256) void cvt_omega(const float* __restrict__ omq,
                                                 const float* __restrict__ omk,
                                                 __half* __restrict__ omT) {
    int i = blockIdx.x * 256 + threadIdx.x;     // over 2*4096
    int qk = i >> 12, e = i & 4095;
    int m = e >> 6, d = e & 63;
    const float* src = qk ? omk : omq;
    omT[qk * 4096 + m * 64 + d] = __float2half_rn(src[d * 64 + m]);
}

// ---------------- prep: W_eff[k][n] = [s*Wq | s*Wk | Wv] ----------------
__global__ __launch_bounds__(256) void prep_weff(
    const float* __restrict__ Wq, const float* __restrict__ Wk,
    const float* __restrict__ Wv, float* __restrict__ Weff) {
    const int k = blockIdx.y;
    const int n = blockIdx.x * 256 + threadIdx.x;
    float r;
    if (n < 512)       r = Wq[k * 512 + n] * 0.125f;
    else if (n < 1024) r = Wk[k * 512 + n - 512] * 0.125f;
    else               r = Wv[k * 512 + n - 1024];
    Weff[k * NC1 + n] = r;
}

// ---------------- prep: transpose + split W [512 x N] -> hi/lo [N x 512] ----------------
__global__ void tsplit(const float* __restrict__ W, int N,
                       __half* __restrict__ Whi, __half* __restrict__ Wlo) {
    __shared__ float t[32][33];
    const int k0 = blockIdx.y * 32, n0 = blockIdx.x * 32;
#pragma unroll
    for (int i = 0; i < 4; i++) {
        int r = threadIdx.y + i * 8;
        t[r][threadIdx.x] = W[(k0 + r) * N + n0 + threadIdx.x];
    }
    __syncthreads();
#pragma unroll
    for (int i = 0; i < 4; i++) {
        int n = threadIdx.y + i * 8, k = threadIdx.x;
        float v = t[k][n];
        __half hi = __float2half_rn(v);
        __half lo = __float2half_rn(v - __half2float(hi));
        long ob = (long)(n0 + n) * EMB + k0 + k;
        Whi[ob] = hi; Wlo[ob] = lo;
    }
}

// ---------------- shared GEMM geometry (proven skeleton) ----------------
#define BM 128
#define BN 256
#define BK 64
#define ROWB 144                       // padded row bytes (72 halves)
#define A_TILE (BM * ROWB)             // 18432
#define B_TILE (BN * ROWB)             // 36864
#define KCH (EMB / BK)                 // 8
#define STAGE1  (A_TILE + B_TILE)      // 55296
#define SMEMSZ1 (2 * STAGE1)           // 110592

// mainloop shared by both epilogues
#define GEMM1_BODY(EPILOGUE)                                                      \
    extern __shared__ __align__(16) char smraw[];                                 \
    const uint32_t sb = smem_u32(smraw);                                          \
    const int tid = threadIdx.x, wid = tid >> 5, lane = tid & 31;                 \
    const int wr = wid >> 2, wc = wid & 3;                                        \
    const long row0 = (long)blockIdx.y * BM;                                      \
    const int  col0 = blockIdx.x * BN;                                            \
    const __half* Ag  = Ah  + row0 * EMB;                                         \
    const __half* Bgh = Bhi + (long)col0 * EMB;                                   \
    auto load_tiles = [&](int ch, int s) {                                        \
        uint32_t base = sb + s * STAGE1;                                          \
        _Pragma("unroll")                                                         \
        for (int i = 0; i < 4; i++) {                                             \
            int f = tid + i * 256; int r = f >> 3, c = f & 7;                     \
            CP16(base + r * ROWB + c * 16, Ag + ch * BK + (long)r * EMB + c * 8); \
        }                                                                         \
        _Pragma("unroll")                                                         \
        for (int i = 0; i < 8; i++) {                                             \
            int f = tid + i * 256; int r = f >> 3, c = f & 7;                     \
            CP16(base + A_TILE + r * ROWB + c * 16,                               \
                 Bgh + ch * BK + (long)r * EMB + c * 8);                          \
        }                                                                         \
    };                                                                            \
    float acc[4][8][4];                                                           \
    _Pragma("unroll")                                                             \
    for (int i = 0; i < 4; i++)                                                   \
        _Pragma("unroll")                                                         \
        for (int j = 0; j < 8; j++)                                               \
            _Pragma("unroll")                                                     \
            for (int t = 0; t < 4; t++) acc[i][j][t] = 0.f;                       \
    load_tiles(0, 0);                                                             \
    CP_COMMIT();                                                                  \
    const uint32_t aRow = (uint32_t)(wr * 64 + (lane & 15)) * ROWB;               \
    const uint32_t aCol = (uint32_t)((lane >> 4) * 8) * 2;                        \
    const uint32_t bRow = (uint32_t)(wc * 64 + (lane & 7) + ((lane >> 4) & 1) * 8) * ROWB; \
    const uint32_t bCol = (uint32_t)(((lane >> 3) & 1) * 8) * 2;                  \
    for (int ch = 0; ch < KCH; ch++) {                                            \
        const int st = ch & 1;                                                    \
        if (ch + 1 < KCH) { load_tiles(ch + 1, st ^ 1); CP_COMMIT(); CP_WAIT1(); }\
        else              { CP_WAIT0(); }                                         \
        __syncthreads();                                                          \
        const uint32_t stB = sb + st * STAGE1;                                    \
        const uint32_t AB = stB, BhB = stB + A_TILE;                              \
        _Pragma("unroll")                                                         \
        for (int kk = 0; kk < BK; kk += 16) {                                     \
            uint32_t af[4][4], bh[8][2];                                          \
            _Pragma("unroll")                                                     \
            for (int np = 0; np < 4; np++) {                                      \
                uint32_t off = bRow + (uint32_t)(np * 16) * ROWB + kk * 2 + bCol; \
                LDSM4(bh[2*np][0], bh[2*np][1], bh[2*np+1][0], bh[2*np+1][1], BhB + off); \
            }                                                                     \
            _Pragma("unroll")                                                     \
            for (int mi = 0; mi < 4; mi++) {                                      \
                uint32_t off = aRow + (uint32_t)(mi * 16) * ROWB + kk * 2 + aCol; \
                LDSM4(af[mi][0], af[mi][1], af[mi][2], af[mi][3], AB + off);      \
            }                                                                     \
            _Pragma("unroll")                                                     \
            for (int mi = 0; mi < 4; mi++)                                        \
                _Pragma("unroll")                                                 \
                for (int ni = 0; ni < 8; ni++)                                    \
                    mma16816(acc[mi][ni], af[mi], bh[ni]);                        \
        }                                                                         \
        __syncthreads();                                                          \
    }                                                                             \
    const int qr = lane >> 2;                                                     \
    const int qc = (lane & 3) * 2;                                                \
    EPILOGUE

// 1-term GEMM, fp32 output (gemm2: output projection)
__global__ void __launch_bounds__(256, 1) gemm_f32(
    const __half* __restrict__ Ah, const __half* __restrict__ Bhi,
    float* __restrict__ C, int ldC) {
    GEMM1_BODY(
#pragma unroll
        for (int mi = 0; mi < 4; mi++) {
            long r0 = row0 + wr * 64 + mi * 16 + qr;
#pragma unroll
            for (int ni = 0; ni < 8; ni++) {
                int cb = col0 + wc * 64 + ni * 8 + qc;
                *(float2*)(C + r0 * ldC + cb)       = make_float2(acc[mi][ni][0], acc[mi][ni][1]);
                *(float2*)(C + (r0 + 8) * ldC + cb) = make_float2(acc[mi][ni][2], acc[mi][ni][3]);
            }
        }
    )
}

// 1-term GEMM, fp16 output (gemm1: projections -> Yh)
__global__ void __launch_bounds__(256, 1) gemm_f16(
    const __half* __restrict__ Ah, const __half* __restrict__ Bhi,
    __half* __restrict__ C, int ldC) {
    GEMM1_BODY(
#pragma unroll
        for (int mi = 0; mi < 4; mi++) {
            long r0 = row0 + wr * 64 + mi * 16 + qr;
#pragma unroll
            for (int ni = 0; ni < 8; ni++) {
                int cb = col0 + wc * 64 + ni * 8 + qc;
                *(__half2*)(C + r0 * ldC + cb)       = __floats2half2_rn(acc[mi][ni][0], acc[mi][ni][1]);
                *(__half2*)(C + (r0 + 8) * ldC + cb) = __floats2half2_rn(acc[mi][ni][2], acc[mi][ni][3]);
            }
        }
    )
}

// ---------------- phi via HMMA: f = Q@omega (K=64), fused norm+exp ----------------
__global__ __launch_bounds__(128) void phi_mma(
    const __half* __restrict__ Yh, const __half* __restrict__ omT,
    float* __restrict__ Qphi, float* __restrict__ Kphi) {
    __shared__ __align__(16) __half At[128 * 72];
    __shared__ __align__(16) __half Bt[64 * 72];
    __shared__ float rowss[128];
    const int tid = threadIdx.x, lane = tid & 31, wid = tid >> 5;
    const int qk = blockIdx.y >> 3, h = blockIdx.y & 7;
    const long r0 = (long)blockIdx.x * 128;

    const __half* om = omT + qk * 4096;
#pragma unroll
    for (int i = 0; i < 4; i++) {
        int f = tid + i * 128; int m = f >> 3, c8 = f & 7;
        *(uint4*)&Bt[m * 72 + c8 * 8] = *(const uint4*)(om + m * 64 + c8 * 8);
    }

    // Q/K rows already fp16: straight copy + sumsq (8 threads per row)
    const __half* src = Yh + r0 * NC1 + qk * 512 + h * 64;
#pragma unroll
    for (int i = 0; i < 8; i++) {
        int idx = tid + i * 128;               // 1024 slots: 128 rows x 8 chunks8
        int r = idx >> 3, c8 = idx & 7;
        uint4 v = *(const uint4*)(src + (long)r * NC1 + c8 * 8);
        const __half2* hp = (const __half2*)&v;
        float s4 = 0.f;
#pragma unroll
        for (int j = 0; j < 4; j++) {
            float2 f2 = __half22float2(hp[j]);
            s4 = fmaf(f2.x, f2.x, s4); s4 = fmaf(f2.y, f2.y, s4);
        }
#pragma unroll
        for (int m = 4; m >= 1; m >>= 1)
            s4 += __shfl_xor_sync(0xffffffffu, s4, m, 8);
        if ((tid & 7) == 0) rowss[r] = s4;
        *(uint4*)&At[r * 72 + c8 * 8] = v;
    }
    __syncthreads();

    const uint32_t AB = smem_u32(At), BB = smem_u32(Bt);
    const uint32_t aRow = (uint32_t)(wid * 32 + (lane & 15)) * ROWB;
    const uint32_t aCol = (uint32_t)((lane >> 4) * 8) * 2;
    const uint32_t bRow = (uint32_t)((lane & 7) + ((lane >> 4) & 1) * 8) * ROWB;
    const uint32_t bCol = (uint32_t)(((lane >> 3) & 1) * 8) * 2;

    float acc[2][8][4];
#pragma unroll
    for (int i = 0; i < 2; i++)
#pragma unroll
        for (int j = 0; j < 8; j++)
#pragma unroll
            for (int t = 0; t < 4; t++) acc[i][j][t] = 0.f;

#pragma unroll
    for (int kk = 0; kk < HD; kk += 16) {
        uint32_t af[2][4], bf[8][2];
#pragma unroll
        for (int np = 0; np < 4; np++) {
            uint32_t off = bRow + (uint32_t)(np * 16) * ROWB + kk * 2 + bCol;
            LDSM4(bf[2*np][0], bf[2*np][1], bf[2*np+1][0], bf[2*np+1][1], BB + off);
        }
#pragma unroll
        for (int mi = 0; mi < 2; mi++) {
            uint32_t off = aRow + (uint32_t)(mi * 16) * ROWB + kk * 2 + aCol;
            LDSM4(af[mi][0], af[mi][1], af[mi][2], af[mi][3], AB + off);
        }
#pragma unroll
        for (int mi = 0; mi < 2; mi++)
#pragma unroll
            for (int ni = 0; ni < 8; ni++)
                mma16816(acc[mi][ni], af[mi], bf[ni]);
    }

    const int qr = lane >> 2, qc = (lane & 3) * 2;
    const int b = (int)(r0 >> 14);
    const int sbase = (int)(r0 & 16383);
    float* dst = (qk == 0 ? Qphi : Kphi) + ((long)(b * HEADS + h) * SEQ) * MF;
#pragma unroll
    for (int mi = 0; mi < 2; mi++) {
        int ra = wid * 32 + mi * 16 + qr;
        float nt0 = fmaxf(expf(-0.5f * rowss[ra]),     1e-8f);
        float nt1 = fmaxf(expf(-0.5f * rowss[ra + 8]), 1e-8f);
        long o0 = (long)(sbase + ra) * MF;
        long o1 = (long)(sbase + ra + 8) * MF;
#pragma unroll
        for (int ni = 0; ni < 8; ni++) {
            int cb = ni * 8 + qc;
            dst[o0 + cb]     = nt0 * expf(fminf(acc[mi][ni][0], 50.0f));
            dst[o0 + cb + 1] = nt0 * expf(fminf(acc[mi][ni][1], 50.0f));
            dst[o1 + cb]     = nt1 * expf(fminf(acc[mi][ni][2], 50.0f));
            dst[o1 + cb + 1] = nt1 * expf(fminf(acc[mi][ni][3], 50.0f));
        }
    }
}

// ---------------- KV partials (V read as fp16 from Yh) ----------------
__global__ __launch_bounds__(256) void kv_partial(
    const float* __restrict__ Kphi, const __half* __restrict__ Yh,
    float* __restrict__ KVp, float* __restrict__ Konesp) {
    __shared__ float Ks[32][MF];
    __shared__ float Vs[32][HD];
    const int tid = threadIdx.x;
    const int bh = blockIdx.y, part = blockIdx.x;
    const int b = bh / HEADS, h = bh % HEADS;
    const int s0 = part * SCHUNK;
    const int tr = (tid >> 4) * 4, tc = (tid & 15) * 4;
    float acc[4][4];
#pragma unroll
    for (int i = 0; i < 4; i++)
#pragma unroll
        for (int j = 0; j < 4; j++) acc[i][j] = 0.f;
    float kon = 0.f;

    for (int ss = 0; ss < SCHUNK; ss += 32) {
#pragma unroll
        for (int i = 0; i < 2; i++) {
            int f = tid + i * 256;
            int r = f >> 4, c = (f & 15) * 4;
            long s = (long)s0 + ss + r;
            *reinterpret_cast<float4*>(&Ks[r][c]) =
                *reinterpret_cast<const float4*>(Kphi + ((long)bh * SEQ + s) * MF + c);
            uint2 hv = *reinterpret_cast<const uint2*>(
                Yh + ((long)b * SEQ + s) * NC1 + 1024 + h * HD + c);
            const __half2* hp = (const __half2*)&hv;
            float2 f0 = __half22float2(hp[0]), f1 = __half22float2(hp[1]);
            Vs[r][c] = f0.x; Vs[r][c + 1] = f0.y; Vs[r][c + 2] = f1.x; Vs[r][c + 3] = f1.y;
        }
        __syncthreads();
#pragma unroll
        for (int k = 0; k < 32; k++) {
            float a[4], bb[4];
            *reinterpret_cast<float4*>(a)  = *reinterpret_cast<const float4*>(&Ks[k][tr]);
            *reinterpret_cast<float4*>(bb) = *reinterpret_cast<const float4*>(&Vs[k][tc]);
#pragma unroll
            for (int i = 0; i < 4; i++)
#pragma unroll
                for (int j = 0; j < 4; j++)
                    acc[i][j] = fmaf(a[i], bb[j], acc[i][j]);
        }
        if (tid < MF) {
#pragma unroll
            for (int k = 0; k < 32; k++) kon += Ks[k][tid];
        }
        __syncthreads();
    }
    float* dst = KVp + ((long)bh * NCHUNK + part) * (MF * HD);
#pragma unroll
    for (int i = 0; i < 4; i++) {
        float4 v = make_float4(acc[i][0], acc[i][1], acc[i][2], acc[i][3]);
        *reinterpret_cast<float4*>(dst + (tr + i) * HD + tc) = v;
    }
    if (tid < MF) Konesp[((long)bh * NCHUNK + part) * MF + tid] = kon;
}

__global__ __launch_bounds__(256) void kv_reduce(
    const float* __restrict__ KVp, const float* __restrict__ Konesp,
    float* __restrict__ KV, float* __restrict__ Kones) {
    const int bh = blockIdx.x, tid = threadIdx.x;
    for (int idx = tid; idx < MF * HD; idx += 256) {
        float s = 0.f;
#pragma unroll
        for (int p = 0; p < NCHUNK; p++)
            s += KVp[((long)bh * NCHUNK + p) * (MF * HD) + idx];
        KV[bh * MF * HD + idx] = s;
    }
    if (tid < MF) {
        float s = 0.f;
#pragma unroll
        for (int p = 0; p < NCHUNK; p++)
            s += Konesp[((long)bh * NCHUNK + p) * MF + tid];
        Kones[bh * MF + tid] = s;
    }
}

// ---------------- attn = (Qphi@KV)/(Qphi@Kones), written as fp16 ----------------
__global__ __launch_bounds__(256) void qkv_attn(
    const float* __restrict__ Qphi, const float* __restrict__ KV,
    const float* __restrict__ Kones, __half* __restrict__ Ah) {
    __shared__ float KVs[MF][HD];
    __shared__ float ko[MF];
    __shared__ float q[4][MF];
    const int tid = threadIdx.x;
    const int bh = blockIdx.y;
    const int b = bh / HEADS, h = bh % HEADS;
    const int s0 = blockIdx.x * 256;
#pragma unroll
    for (int i = 0; i < 4; i++) {
        int f = tid + i * 256;
        int m = f >> 4, c = (f & 15) * 4;
        *reinterpret_cast<float4*>(&KVs[m][c]) =
            *reinterpret_cast<const float4*>(KV + (long)bh * MF * HD + m * HD + c);
    }
    if (tid < MF) ko[tid] = Kones[bh * MF + tid];
    __syncthreads();

    const int sub = tid >> 6, t = tid & 63;
    for (int ss = 0; ss < 256; ss += 4) {
        int s = s0 + ss + sub;
        q[sub][t] = Qphi[((long)bh * SEQ + s) * MF + t];
        __syncthreads();
        float num = 0.f, den = 0.f;
#pragma unroll
        for (int m = 0; m < MF; m++) {
            float qm = q[sub][m];
            den = fmaf(qm, ko[m], den);
            num = fmaf(qm, KVs[m][t], num);
        }
        Ah[((long)b * SEQ + s) * EMB + h * HD + t] = __float2half_rn(num / den);
        __syncthreads();
    }
}

// ---------------- launch ----------------
extern "C" void kernel_launch(void* const* d_in, const int* in_sizes, int n_in,
                              void* d_out, int out_size) {
    const float* x   = (const float*)d_in[0];
    const float* Wq  = (const float*)d_in[1];
    const float* Wk  = (const float*)d_in[2];
    const float* Wv  = (const float*)d_in[3];
    const float* Wo  = (const float*)d_in[4];
    const float* omq = (const float*)d_in[5];
    const float* omk = (const float*)d_in[6];
    float* out = (float*)d_out;

    __half *pXh, *pWh1, *pWl1, *pWh2, *pWl2, *pOmT, *pYh;
    float *pWeff, *pQphi, *pKphi, *pKVp, *pKonesp, *pKV, *pKones;
    cudaGetSymbolAddress((void**)&pXh,    g_Xh);
    cudaGetSymbolAddress((void**)&pWeff,  g_Weff);
    cudaGetSymbolAddress((void**)&pWh1,   g_Wh1);
    cudaGetSymbolAddress((void**)&pWl1,   g_Wl1);
    cudaGetSymbolAddress((void**)&pWh2,   g_Wh2);
    cudaGetSymbolAddress((void**)&pWl2,   g_Wl2);
    cudaGetSymbolAddress((void**)&pOmT,   g_omT);
    cudaGetSymbolAddress((void**)&pYh,    g_Yh);
    cudaGetSymbolAddress((void**)&pQphi,  g_Qphi);
    cudaGetSymbolAddress((void**)&pKphi,  g_Kphi);
    cudaGetSymbolAddress((void**)&pKVp,   g_KVp);
    cudaGetSymbolAddress((void**)&pKonesp,g_Konesp);
    cudaGetSymbolAddress((void**)&pKV,    g_KV);
    cudaGetSymbolAddress((void**)&pKones, g_Kones);

    cudaFuncSetAttribute(gemm_f16, cudaFuncAttributeMaxDynamicSharedMemorySize, SMEMSZ1);
    cudaFuncSetAttribute(gemm_f32, cudaFuncAttributeMaxDynamicSharedMemorySize, SMEMSZ1);

    cvt_x<<<(NROWS * EMB) / 256, 256>>>(x, pXh);
    cvt_omega<<<(2 * HD * MF) / 256, 256>>>(omq, omk, pOmT);
    prep_weff<<<dim3(NC1 / 256, EMB), 256>>>(Wq, Wk, Wv, pWeff);
    tsplit<<<dim3(NC1 / 32, EMB / 32), dim3(32, 8)>>>(pWeff, NC1, pWh1, pWl1);
    tsplit<<<dim3(EMB / 32, EMB / 32), dim3(32, 8)>>>(Wo, EMB, pWh2, pWl2);

    gemm_f16<<<dim3(NC1 / BN, NROWS / BM), 256, SMEMSZ1>>>(pXh, pWh1, pYh, NC1);

    phi_mma<<<dim3(NROWS / 128, 16), 128>>>(pYh, pOmT, pQphi, pKphi);

    kv_partial<<<dim3(NCHUNK, BH), 256>>>(pKphi, pYh, pKVp, pKonesp);
    kv_reduce<<<BH, 256>>>(pKVp, pKonesp, pKV, pKones);
    // g_Xh dead after gemm1 -> reuse for attn fp16
    qkv_attn<<<dim3(SEQ / 256, BH), 256>>>(pQphi, pKV, pKones, pXh);

    gemm_f32<<<dim3(EMB / BN, NROWS / BM), 256, SMEMSZ1>>>(pXh, pWh2, out, EMB);
}

// round 17
// speedup vs baseline: 3.2453x; 1.0230x over previous
#include <cuda_runtime.h>
#include <cuda_fp16.h>
#include <math.h>
#include <stdint.h>

#define BATCH 2
#define SEQ   16384
#define EMB   512
#define HEADS 8
#define HD    64
#define MF    64
#define NROWS 32768          // BATCH*SEQ
#define BH    16
#define NC1   1536           // [Q|K|V] columns
#define NCHUNK 16
#define SCHUNK 1024

// ---------------- device scratch ----------------
__device__ __align__(1024) __half g_Xh[(long)NROWS * EMB];
__device__ __align__(1024) float  g_Weff[EMB * NC1];
__device__ __align__(1024) __half g_Wh1[(long)NC1 * EMB];
__device__ __align__(1024) __half g_Wl1[(long)NC1 * EMB];
__device__ __align__(1024) __half g_Wh2[EMB * EMB];
__device__ __align__(1024) __half g_Wl2[EMB * EMB];
__device__ __align__(1024) __half g_omT[2 * HD * MF];   // fp16 omega^T [qk][m][d]
__device__ __align__(1024) __half g_Yh[(long)NROWS * NC1];   // fp16 projections
__device__ __align__(1024) __half g_Qphi[(long)BH * SEQ * MF];   // fp16 phi
__device__ __align__(1024) __half g_Kphi[(long)BH * SEQ * MF];   // fp16 phi
__device__ __align__(1024) float  g_KVp[BH * NCHUNK * MF * HD];
__device__ __align__(1024) float  g_Konesp[BH * NCHUNK * MF];
__device__ __align__(1024) float  g_KV[BH * MF * HD];
__device__ __align__(1024) float  g_Kones[BH * MF];

// ---------------- helpers ----------------
__device__ __forceinline__ uint32_t smem_u32(const void* p) {
    uint32_t a;
    asm("{ .reg .u64 t; cvta.to.shared.u64 t, %1; cvt.u32.u64 %0, t; }" : "=r"(a) : "l"(p));
    return a;
}
#define CP16(dst, src)   asm volatile("cp.async.cg.shared.global [%0], [%1], 16;" :: "r"(dst), "l"(src))
#define CP_COMMIT()      asm volatile("cp.async.commit_group;" ::: "memory")
#define CP_WAIT1()       asm volatile("cp.async.wait_group 1;" ::: "memory")
#define CP_WAIT0()       asm volatile("cp.async.wait_group 0;" ::: "memory")
#define LDSM4(r0,r1,r2,r3,addr) \
    asm volatile("ldmatrix.sync.aligned.m8n8.x4.shared.b16 {%0,%1,%2,%3}, [%4];" \
        : "=r"(r0), "=r"(r1), "=r"(r2), "=r"(r3) : "r"(addr))

__device__ __forceinline__ void mma16816(float* c, const uint32_t* a, const uint32_t* b) {
    asm volatile(
        "mma.sync.aligned.m16n8k16.row.col.f32.f16.f16.f32 "
        "{%0,%1,%2,%3}, {%4,%5,%6,%7}, {%8,%9}, {%0,%1,%2,%3};"
        : "+f"(c[0]), "+f"(c[1]), "+f"(c[2]), "+f"(c[3])
        : "r"(a[0]), "r"(a[1]), "r"(a[2]), "r"(a[3]), "r"(b[0]), "r"(b[1]));
}

// ---------------- prep: x -> fp16 ----------------
__global__ __launch_bounds__(256) void cvt_x(const float* __restrict__ x,
                                             __half* __restrict__ oh) {
    long idx = (long)blockIdx.x * 256 + threadIdx.x;
    oh[idx] = __float2half_rn(x[idx]);
}

// ---------------- prep: omega [d][m] fp32 -> omega^T [m][d] fp16 ----------------
__global__ __launch_bounds__(256) void cvt_omega(const float* __restrict__ omq,
                                                 const float* __restrict__ omk,
                                                 __half* __restrict__ omT) {
    int i = blockIdx.x * 256 + threadIdx.x;     // over 2*4096
    int qk = i >> 12, e = i & 4095;
    int m = e >> 6, d = e & 63;
    const float* src = qk ? omk : omq;
    omT[qk * 4096 + m * 64 + d] = __float2half_rn(src[d * 64 + m]);
}

// ---------------- prep: W_eff[k][n] = [s*Wq | s*Wk | Wv] ----------------
__global__ __launch_bounds__(256) void prep_weff(
    const float* __restrict__ Wq, const float* __restrict__ Wk,
    const float* __restrict__ Wv, float* __restrict__ Weff) {
    const int k = blockIdx.y;
    const int n = blockIdx.x * 256 + threadIdx.x;
    float r;
    if (n < 512)       r = Wq[k * 512 + n] * 0.125f;
    else if (n < 1024) r = Wk[k * 512 + n - 512] * 0.125f;
    else               r = Wv[k * 512 + n - 1024];
    Weff[k * NC1 + n] = r;
}

// ---------------- prep: transpose + split W [512 x N] -> hi/lo [N x 512] ----------------
__global__ void tsplit(const float* __restrict__ W, int N,
                       __half* __restrict__ Whi, __half* __restrict__ Wlo) {
    __shared__ float t[32][33];
    const int k0 = blockIdx.y * 32, n0 = blockIdx.x * 32;
#pragma unroll
    for (int i = 0; i < 4; i++) {
        int r = threadIdx.y + i * 8;
        t[r][threadIdx.x] = W[(k0 + r) * N + n0 + threadIdx.x];
    }
    __syncthreads();
#pragma unroll
    for (int i = 0; i < 4; i++) {
        int n = threadIdx.y + i * 8, k = threadIdx.x;
        float v = t[k][n];
        __half hi = __float2half_rn(v);
        __half lo = __float2half_rn(v - __half2float(hi));
        long ob = (long)(n0 + n) * EMB + k0 + k;
        Whi[ob] = hi; Wlo[ob] = lo;
    }
}

// ---------------- shared GEMM geometry (proven skeleton) ----------------
#define BM 128
#define BN 256
#define BK 64
#define ROWB 144                       // padded row bytes (72 halves)
#define A_TILE (BM * ROWB)             // 18432
#define B_TILE (BN * ROWB)             // 36864
#define KCH (EMB / BK)                 // 8
#define STAGE1  (A_TILE + B_TILE)      // 55296
#define SMEMSZ1 (2 * STAGE1)           // 110592

// mainloop shared by both epilogues
#define GEMM1_BODY(EPILOGUE)                                                      \
    extern __shared__ __align__(16) char smraw[];                                 \
    const uint32_t sb = smem_u32(smraw);                                          \
    const int tid = threadIdx.x, wid = tid >> 5, lane = tid & 31;                 \
    const int wr = wid >> 2, wc = wid & 3;                                        \
    const long row0 = (long)blockIdx.y * BM;                                      \
    const int  col0 = blockIdx.x * BN;                                            \
    const __half* Ag  = Ah  + row0 * EMB;                                         \
    const __half* Bgh = Bhi + (long)col0 * EMB;                                   \
    auto load_tiles = [&](int ch, int s) {                                        \
        uint32_t base = sb + s * STAGE1;                                          \
        _Pragma("unroll")                                                         \
        for (int i = 0; i < 4; i++) {                                             \
            int f = tid + i * 256; int r = f >> 3, c = f & 7;                     \
            CP16(base + r * ROWB + c * 16, Ag + ch * BK + (long)r * EMB + c * 8); \
        }                                                                         \
        _Pragma("unroll")                                                         \
        for (int i = 0; i < 8; i++) {                                             \
            int f = tid + i * 256; int r = f >> 3, c = f & 7;                     \
            CP16(base + A_TILE + r * ROWB + c * 16,                               \
                 Bgh + ch * BK + (long)r * EMB + c * 8);                          \
        }                                                                         \
    };                                                                            \
    float acc[4][8][4];                                                           \
    _Pragma("unroll")                                                             \
    for (int i = 0; i < 4; i++)                                                   \
        _Pragma("unroll")                                                         \
        for (int j = 0; j < 8; j++)                                               \
            _Pragma("unroll")                                                     \
            for (int t = 0; t < 4; t++) acc[i][j][t] = 0.f;                       \
    load_tiles(0, 0);                                                             \
    CP_COMMIT();                                                                  \
    const uint32_t aRow = (uint32_t)(wr * 64 + (lane & 15)) * ROWB;               \
    const uint32_t aCol = (uint32_t)((lane >> 4) * 8) * 2;                        \
    const uint32_t bRow = (uint32_t)(wc * 64 + (lane & 7) + ((lane >> 4) & 1) * 8) * ROWB; \
    const uint32_t bCol = (uint32_t)(((lane >> 3) & 1) * 8) * 2;                  \
    for (int ch = 0; ch < KCH; ch++) {                                            \
        const int st = ch & 1;                                                    \
        if (ch + 1 < KCH) { load_tiles(ch + 1, st ^ 1); CP_COMMIT(); CP_WAIT1(); }\
        else              { CP_WAIT0(); }                                         \
        __syncthreads();                                                          \
        const uint32_t stB = sb + st * STAGE1;                                    \
        const uint32_t AB = stB, BhB = stB + A_TILE;                              \
        _Pragma("unroll")                                                         \
        for (int kk = 0; kk < BK; kk += 16) {                                     \
            uint32_t af[4][4], bh[8][2];                                          \
            _Pragma("unroll")                                                     \
            for (int np = 0; np < 4; np++) {                                      \
                uint32_t off = bRow + (uint32_t)(np * 16) * ROWB + kk * 2 + bCol; \
                LDSM4(bh[2*np][0], bh[2*np][1], bh[2*np+1][0], bh[2*np+1][1], BhB + off); \
            }                                                                     \
            _Pragma("unroll")                                                     \
            for (int mi = 0; mi < 4; mi++) {                                      \
                uint32_t off = aRow + (uint32_t)(mi * 16) * ROWB + kk * 2 + aCol; \
                LDSM4(af[mi][0], af[mi][1], af[mi][2], af[mi][3], AB + off);      \
            }                                                                     \
            _Pragma("unroll")                                                     \
            for (int mi = 0; mi < 4; mi++)                                        \
                _Pragma("unroll")                                                 \
                for (int ni = 0; ni < 8; ni++)                                    \
                    mma16816(acc[mi][ni], af[mi], bh[ni]);                        \
        }                                                                         \
        __syncthreads();                                                          \
    }                                                                             \
    const int qr = lane >> 2;                                                     \
    const int qc = (lane & 3) * 2;                                                \
    EPILOGUE

// 1-term GEMM, fp32 output (gemm2: output projection)
__global__ void __launch_bounds__(256, 1) gemm_f32(
    const __half* __restrict__ Ah, const __half* __restrict__ Bhi,
    float* __restrict__ C, int ldC) {
    GEMM1_BODY(
#pragma unroll
        for (int mi = 0; mi < 4; mi++) {
            long r0 = row0 + wr * 64 + mi * 16 + qr;
#pragma unroll
            for (int ni = 0; ni < 8; ni++) {
                int cb = col0 + wc * 64 + ni * 8 + qc;
                *(float2*)(C + r0 * ldC + cb)       = make_float2(acc[mi][ni][0], acc[mi][ni][1]);
                *(float2*)(C + (r0 + 8) * ldC + cb) = make_float2(acc[mi][ni][2], acc[mi][ni][3]);
            }
        }
    )
}

// 1-term GEMM, fp16 output (gemm1: projections -> Yh)
__global__ void __launch_bounds__(256, 1) gemm_f16(
    const __half* __restrict__ Ah, const __half* __restrict__ Bhi,
    __half* __restrict__ C, int ldC) {
    GEMM1_BODY(
#pragma unroll
        for (int mi = 0; mi < 4; mi++) {
            long r0 = row0 + wr * 64 + mi * 16 + qr;
#pragma unroll
            for (int ni = 0; ni < 8; ni++) {
                int cb = col0 + wc * 64 + ni * 8 + qc;
                *(__half2*)(C + r0 * ldC + cb)       = __floats2half2_rn(acc[mi][ni][0], acc[mi][ni][1]);
                *(__half2*)(C + (r0 + 8) * ldC + cb) = __floats2half2_rn(acc[mi][ni][2], acc[mi][ni][3]);
            }
        }
    )
}

// ---------------- phi via HMMA: f = Q@omega (K=64), fused norm+exp, fp16 out ----------------
__global__ __launch_bounds__(128) void phi_mma(
    const __half* __restrict__ Yh, const __half* __restrict__ omT,
    __half* __restrict__ Qphi, __half* __restrict__ Kphi) {
    __shared__ __align__(16) __half At[128 * 72];
    __shared__ __align__(16) __half Bt[64 * 72];
    __shared__ float rowss[128];
    const int tid = threadIdx.x, lane = tid & 31, wid = tid >> 5;
    const int qk = blockIdx.y >> 3, h = blockIdx.y & 7;
    const long r0 = (long)blockIdx.x * 128;

    const __half* om = omT + qk * 4096;
#pragma unroll
    for (int i = 0; i < 4; i++) {
        int f = tid + i * 128; int m = f >> 3, c8 = f & 7;
        *(uint4*)&Bt[m * 72 + c8 * 8] = *(const uint4*)(om + m * 64 + c8 * 8);
    }

    // Q/K rows already fp16: straight copy + sumsq (8 threads per row)
    const __half* src = Yh + r0 * NC1 + qk * 512 + h * 64;
#pragma unroll
    for (int i = 0; i < 8; i++) {
        int idx = tid + i * 128;               // 1024 slots: 128 rows x 8 chunks8
        int r = idx >> 3, c8 = idx & 7;
        uint4 v = *(const uint4*)(src + (long)r * NC1 + c8 * 8);
        const __half2* hp = (const __half2*)&v;
        float s4 = 0.f;
#pragma unroll
        for (int j = 0; j < 4; j++) {
            float2 f2 = __half22float2(hp[j]);
            s4 = fmaf(f2.x, f2.x, s4); s4 = fmaf(f2.y, f2.y, s4);
        }
#pragma unroll
        for (int m = 4; m >= 1; m >>= 1)
            s4 += __shfl_xor_sync(0xffffffffu, s4, m, 8);
        if ((tid & 7) == 0) rowss[r] = s4;
        *(uint4*)&At[r * 72 + c8 * 8] = v;
    }
    __syncthreads();

    const uint32_t AB = smem_u32(At), BB = smem_u32(Bt);
    const uint32_t aRow = (uint32_t)(wid * 32 + (lane & 15)) * ROWB;
    const uint32_t aCol = (uint32_t)((lane >> 4) * 8) * 2;
    const uint32_t bRow = (uint32_t)((lane & 7) + ((lane >> 4) & 1) * 8) * ROWB;
    const uint32_t bCol = (uint32_t)(((lane >> 3) & 1) * 8) * 2;

    float acc[2][8][4];
#pragma unroll
    for (int i = 0; i < 2; i++)
#pragma unroll
        for (int j = 0; j < 8; j++)
#pragma unroll
            for (int t = 0; t < 4; t++) acc[i][j][t] = 0.f;

#pragma unroll
    for (int kk = 0; kk < HD; kk += 16) {
        uint32_t af[2][4], bf[8][2];
#pragma unroll
        for (int np = 0; np < 4; np++) {
            uint32_t off = bRow + (uint32_t)(np * 16) * ROWB + kk * 2 + bCol;
            LDSM4(bf[2*np][0], bf[2*np][1], bf[2*np+1][0], bf[2*np+1][1], BB + off);
        }
#pragma unroll
        for (int mi = 0; mi < 2; mi++) {
            uint32_t off = aRow + (uint32_t)(mi * 16) * ROWB + kk * 2 + aCol;
            LDSM4(af[mi][0], af[mi][1], af[mi][2], af[mi][3], AB + off);
        }
#pragma unroll
        for (int mi = 0; mi < 2; mi++)
#pragma unroll
            for (int ni = 0; ni < 8; ni++)
                mma16816(acc[mi][ni], af[mi], bf[ni]);
    }

    const int qr = lane >> 2, qc = (lane & 3) * 2;
    const int b = (int)(r0 >> 14);
    const int sbase = (int)(r0 & 16383);
    __half* dst = (qk == 0 ? Qphi : Kphi) + ((long)(b * HEADS + h) * SEQ) * MF;
#pragma unroll
    for (int mi = 0; mi < 2; mi++) {
        int ra = wid * 32 + mi * 16 + qr;
        float nt0 = fmaxf(expf(-0.5f * rowss[ra]),     1e-8f);
        float nt1 = fmaxf(expf(-0.5f * rowss[ra + 8]), 1e-8f);
        long o0 = (long)(sbase + ra) * MF;
        long o1 = (long)(sbase + ra + 8) * MF;
#pragma unroll
        for (int ni = 0; ni < 8; ni++) {
            int cb = ni * 8 + qc;
            *(__half2*)&dst[o0 + cb] = __floats2half2_rn(
                nt0 * expf(fminf(acc[mi][ni][0], 50.0f)),
                nt0 * expf(fminf(acc[mi][ni][1], 50.0f)));
            *(__half2*)&dst[o1 + cb] = __floats2half2_rn(
                nt1 * expf(fminf(acc[mi][ni][2], 50.0f)),
                nt1 * expf(fminf(acc[mi][ni][3], 50.0f)));
        }
    }
}

// ---------------- KV partials (Kphi fp16, V fp16 from Yh) ----------------
__global__ __launch_bounds__(256) void kv_partial(
    const __half* __restrict__ Kphi, const __half* __restrict__ Yh,
    float* __restrict__ KVp, float* __restrict__ Konesp) {
    __shared__ float Ks[32][MF];
    __shared__ float Vs[32][HD];
    const int tid = threadIdx.x;
    const int bh = blockIdx.y, part = blockIdx.x;
    const int b = bh / HEADS, h = bh % HEADS;
    const int s0 = part * SCHUNK;
    const int tr = (tid >> 4) * 4, tc = (tid & 15) * 4;
    float acc[4][4];
#pragma unroll
    for (int i = 0; i < 4; i++)
#pragma unroll
        for (int j = 0; j < 4; j++) acc[i][j] = 0.f;
    float kon = 0.f;

    for (int ss = 0; ss < SCHUNK; ss += 32) {
#pragma unroll
        for (int i = 0; i < 2; i++) {
            int f = tid + i * 256;
            int r = f >> 4, c = (f & 15) * 4;
            long s = (long)s0 + ss + r;
            uint2 kv2 = *reinterpret_cast<const uint2*>(
                Kphi + ((long)bh * SEQ + s) * MF + c);
            const __half2* kp = (const __half2*)&kv2;
            float2 k0 = __half22float2(kp[0]), k1 = __half22float2(kp[1]);
            Ks[r][c] = k0.x; Ks[r][c + 1] = k0.y; Ks[r][c + 2] = k1.x; Ks[r][c + 3] = k1.y;
            uint2 hv = *reinterpret_cast<const uint2*>(
                Yh + ((long)b * SEQ + s) * NC1 + 1024 + h * HD + c);
            const __half2* hp = (const __half2*)&hv;
            float2 f0 = __half22float2(hp[0]), f1 = __half22float2(hp[1]);
            Vs[r][c] = f0.x; Vs[r][c + 1] = f0.y; Vs[r][c + 2] = f1.x; Vs[r][c + 3] = f1.y;
        }
        __syncthreads();
#pragma unroll
        for (int k = 0; k < 32; k++) {
            float a[4], bb[4];
            *reinterpret_cast<float4*>(a)  = *reinterpret_cast<const float4*>(&Ks[k][tr]);
            *reinterpret_cast<float4*>(bb) = *reinterpret_cast<const float4*>(&Vs[k][tc]);
#pragma unroll
            for (int i = 0; i < 4; i++)
#pragma unroll
                for (int j = 0; j < 4; j++)
                    acc[i][j] = fmaf(a[i], bb[j], acc[i][j]);
        }
        if (tid < MF) {
#pragma unroll
            for (int k = 0; k < 32; k++) kon += Ks[k][tid];
        }
        __syncthreads();
    }
    float* dst = KVp + ((long)bh * NCHUNK + part) * (MF * HD);
#pragma unroll
    for (int i = 0; i < 4; i++) {
        float4 v = make_float4(acc[i][0], acc[i][1], acc[i][2], acc[i][3]);
        *reinterpret_cast<float4*>(dst + (tr + i) * HD + tc) = v;
    }
    if (tid < MF) Konesp[((long)bh * NCHUNK + part) * MF + tid] = kon;
}

__global__ __launch_bounds__(256) void kv_reduce(
    const float* __restrict__ KVp, const float* __restrict__ Konesp,
    float* __restrict__ KV, float* __restrict__ Kones) {
    const int bh = blockIdx.x, tid = threadIdx.x;
    for (int idx = tid; idx < MF * HD; idx += 256) {
        float s = 0.f;
#pragma unroll
        for (int p = 0; p < NCHUNK; p++)
            s += KVp[((long)bh * NCHUNK + p) * (MF * HD) + idx];
        KV[bh * MF * HD + idx] = s;
    }
    if (tid < MF) {
        float s = 0.f;
#pragma unroll
        for (int p = 0; p < NCHUNK; p++)
            s += Konesp[((long)bh * NCHUNK + p) * MF + tid];
        Kones[bh * MF + tid] = s;
    }
}

// ---------------- attn = (Qphi@KV)/(Qphi@Kones), Qphi fp16, written as fp16 ----------------
__global__ __launch_bounds__(256) void qkv_attn(
    const __half* __restrict__ Qphi, const float* __restrict__ KV,
    const float* __restrict__ Kones, __half* __restrict__ Ah) {
    __shared__ float KVs[MF][HD];
    __shared__ float ko[MF];
    __shared__ float q[4][MF];
    const int tid = threadIdx.x;
    const int bh = blockIdx.y;
    const int b = bh / HEADS, h = bh % HEADS;
    const int s0 = blockIdx.x * 256;
#pragma unroll
    for (int i = 0; i < 4; i++) {
        int f = tid + i * 256;
        int m = f >> 4, c = (f & 15) * 4;
        *reinterpret_cast<float4*>(&KVs[m][c]) =
            *reinterpret_cast<const float4*>(KV + (long)bh * MF * HD + m * HD + c);
    }
    if (tid < MF) ko[tid] = Kones[bh * MF + tid];
    __syncthreads();

    const int sub = tid >> 6, t = tid & 63;
    for (int ss = 0; ss < 256; ss += 4) {
        int s = s0 + ss + sub;
        q[sub][t] = __half2float(Qphi[((long)bh * SEQ + s) * MF + t]);
        __syncthreads();
        float num = 0.f, den = 0.f;
#pragma unroll
        for (int m = 0; m < MF; m++) {
            float qm = q[sub][m];
            den = fmaf(qm, ko[m], den);
            num = fmaf(qm, KVs[m][t], num);
        }
        Ah[((long)b * SEQ + s) * EMB + h * HD + t] = __float2half_rn(num / den);
        __syncthreads();
    }
}

// ---------------- launch ----------------
extern "C" void kernel_launch(void* const* d_in, const int* in_sizes, int n_in,
                              void* d_out, int out_size) {
    const float* x   = (const float*)d_in[0];
    const float* Wq  = (const float*)d_in[1];
    const float* Wk  = (const float*)d_in[2];
    const float* Wv  = (const float*)d_in[3];
    const float* Wo  = (const float*)d_in[4];
    const float* omq = (const float*)d_in[5];
    const float* omk = (const float*)d_in[6];
    float* out = (float*)d_out;

    __half *pXh, *pWh1, *pWl1, *pWh2, *pWl2, *pOmT, *pYh, *pQphi, *pKphi;
    float *pWeff, *pKVp, *pKonesp, *pKV, *pKones;
    cudaGetSymbolAddress((void**)&pXh,    g_Xh);
    cudaGetSymbolAddress((void**)&pWeff,  g_Weff);
    cudaGetSymbolAddress((void**)&pWh1,   g_Wh1);
    cudaGetSymbolAddress((void**)&pWl1,   g_Wl1);
    cudaGetSymbolAddress((void**)&pWh2,   g_Wh2);
    cudaGetSymbolAddress((void**)&pWl2,   g_Wl2);
    cudaGetSymbolAddress((void**)&pOmT,   g_omT);
    cudaGetSymbolAddress((void**)&pYh,    g_Yh);
    cudaGetSymbolAddress((void**)&pQphi,  g_Qphi);
    cudaGetSymbolAddress((void**)&pKphi,  g_Kphi);
    cudaGetSymbolAddress((void**)&pKVp,   g_KVp);
    cudaGetSymbolAddress((void**)&pKonesp,g_Konesp);
    cudaGetSymbolAddress((void**)&pKV,    g_KV);
    cudaGetSymbolAddress((void**)&pKones, g_Kones);

    cudaFuncSetAttribute(gemm_f16, cudaFuncAttributeMaxDynamicSharedMemorySize, SMEMSZ1);
    cudaFuncSetAttribute(gemm_f32, cudaFuncAttributeMaxDynamicSharedMemorySize, SMEMSZ1);

    // Reordered so the GEMM lands in the ncu capture slot (previously tsplit).
    cvt_x<<<(NROWS * EMB) / 256, 256>>>(x, pXh);
    prep_weff<<<dim3(NC1 / 256, EMB), 256>>>(Wq, Wk, Wv, pWeff);
    tsplit<<<dim3(NC1 / 32, EMB / 32), dim3(32, 8)>>>(pWeff, NC1, pWh1, pWl1);
    cvt_omega<<<(2 * HD * MF) / 256, 256>>>(omq, omk, pOmT);

    gemm_f16<<<dim3(NC1 / BN, NROWS / BM), 256, SMEMSZ1>>>(pXh, pWh1, pYh, NC1);

    phi_mma<<<dim3(NROWS / 128, 16), 128>>>(pYh, pOmT, pQphi, pKphi);

    kv_partial<<<dim3(NCHUNK, BH), 256>>>(pKphi, pYh, pKVp, pKonesp);
    kv_reduce<<<BH, 256>>>(pKVp, pKonesp, pKV, pKones);
    // g_Xh dead after gemm1 -> reuse for attn fp16
    qkv_attn<<<dim3(SEQ / 256, BH), 256>>>(pQphi, pKV, pKones, pXh);

    tsplit<<<dim3(EMB / 32, EMB / 32), dim3(32, 8)>>>(Wo, EMB, pWh2, pWl2);
    gemm_f32<<<dim3(EMB / BN, NROWS / BM), 256, SMEMSZ1>>>(pXh, pWh2, out, EMB);
}